// round 1
// baseline (speedup 1.0000x reference)
#include <cuda_runtime.h>
#include <math.h>

// Problem constants
#define BATCH 8
#define NSEQ  1024
#define CDIM  768
#define NHEAD 12
#define DHEAD 64
#define MROWS (BATCH * NSEQ)   // 8192
#define QK_SCALE 0.125f        // 64^-0.5

// Scratch: device globals (allocation-free kernel_launch)
__device__ float g_Q[BATCH * NHEAD * NSEQ * DHEAD];
__device__ float g_K[BATCH * NHEAD * NSEQ * DHEAD];
__device__ float g_V[BATCH * NHEAD * NSEQ * DHEAD];
__device__ float g_O[BATCH * NSEQ * CDIM];

// ---------------------------------------------------------------------------
// Kernel 1: QKV GEMM.  out[m, o] = sum_k x[m,k] * qkv_w[o,k]
// Scatters result into g_Q / g_K / g_V with layout [B, H, N, D]; Q gets *SCALE.
// Tiling: 128x128x8, 256 threads, 8x8 per-thread register tile.
// M = 8192, N = 2304, K = 768  (all tile-divisible, no bounds checks).
// ---------------------------------------------------------------------------
__global__ __launch_bounds__(256) void qkv_gemm_kernel(
    const float* __restrict__ x, const float* __restrict__ w)
{
    __shared__ float As[8][128];
    __shared__ float Bs[8][128];

    const int m0 = blockIdx.y * 128;
    const int n0 = blockIdx.x * 128;
    const int tid = threadIdx.x;
    const int tx = tid & 15;          // 0..15
    const int ty = tid >> 4;          // 0..15

    // load indexing: threads 0..127 handle k-offset 0, 128..255 handle k-offset 4
    const int lrow = tid & 127;
    const int lk   = (tid >> 7) * 4;

    float acc[8][8];
#pragma unroll
    for (int i = 0; i < 8; i++)
#pragma unroll
        for (int j = 0; j < 8; j++) acc[i][j] = 0.0f;

    for (int k0 = 0; k0 < 768; k0 += 8) {
        float4 av = *(const float4*)&x[(m0 + lrow) * 768 + k0 + lk];
        float4 bv = *(const float4*)&w[(n0 + lrow) * 768 + k0 + lk];
        __syncthreads();   // protect previous iteration's reads
        As[lk + 0][lrow] = av.x; As[lk + 1][lrow] = av.y;
        As[lk + 2][lrow] = av.z; As[lk + 3][lrow] = av.w;
        Bs[lk + 0][lrow] = bv.x; Bs[lk + 1][lrow] = bv.y;
        Bs[lk + 2][lrow] = bv.z; Bs[lk + 3][lrow] = bv.w;
        __syncthreads();

#pragma unroll
        for (int k = 0; k < 8; k++) {
            float4 a0 = *(float4*)&As[k][ty * 8];
            float4 a1 = *(float4*)&As[k][ty * 8 + 4];
            float4 b0 = *(float4*)&Bs[k][tx * 8];
            float4 b1 = *(float4*)&Bs[k][tx * 8 + 4];
            float ar[8] = {a0.x, a0.y, a0.z, a0.w, a1.x, a1.y, a1.z, a1.w};
            float br[8] = {b0.x, b0.y, b0.z, b0.w, b1.x, b1.y, b1.z, b1.w};
#pragma unroll
            for (int i = 0; i < 8; i++)
#pragma unroll
                for (int j = 0; j < 8; j++) acc[i][j] += ar[i] * br[j];
        }
    }

    // epilogue: scatter into Q/K/V  [B,H,N,D]
#pragma unroll
    for (int i = 0; i < 8; i++) {
        const int m = m0 + ty * 8 + i;
        const int b = m >> 10;
        const int n = m & 1023;
#pragma unroll
        for (int j = 0; j < 8; j++) {
            const int o = n0 + tx * 8 + j;
            const int which = o / 768;
            const int r = o - which * 768;
            const int h = r >> 6;
            const int d = r & 63;
            const int idx = ((b * NHEAD + h) * NSEQ + n) * DHEAD + d;
            const float v = acc[i][j];
            if (which == 0)      g_Q[idx] = v * QK_SCALE;
            else if (which == 1) g_K[idx] = v;
            else                 g_V[idx] = v;
        }
    }
}

// ---------------------------------------------------------------------------
// Kernel 2: flash attention.  One block per (q-tile of 64 rows, head, batch).
// 128 threads: tx 0..7 (key/dim groups), ty 0..15 (row groups of 4).
// Streams keys/values in tiles of 32 with online softmax.
// Q is pre-scaled. Output written to g_O in [B, N, C] layout for the proj GEMM.
// ---------------------------------------------------------------------------
__global__ __launch_bounds__(128) void flash_attn_kernel()
{
    __shared__ float QsT[64][68];   // [d][row]  (transposed for vectorized LDS)
    __shared__ float KsT[64][36];   // [d][key]
    __shared__ float Vs[32][68];    // [key][d]
    __shared__ float Ss[64][36];    // [row][key]  (P tile)

    const int qt = blockIdx.x;      // 0..15
    const int h  = blockIdx.y;      // 0..11
    const int b  = blockIdx.z;      // 0..7
    const int tid = threadIdx.x;
    const int tx = tid & 7;         // 0..7
    const int ty = tid >> 3;        // 0..15

    const float* Qb = g_Q + ((b * NHEAD + h) * NSEQ + qt * 64) * DHEAD;
    const float* Kb = g_K + ((size_t)(b * NHEAD + h) * NSEQ) * DHEAD;
    const float* Vb = g_V + ((size_t)(b * NHEAD + h) * NSEQ) * DHEAD;

    // Load Q tile transposed: QsT[d][row]
    for (int i = tid; i < 64 * 16; i += 128) {
        const int r  = i >> 4;
        const int d4 = (i & 15) * 4;
        float4 v = *(const float4*)&Qb[r * 64 + d4];
        QsT[d4 + 0][r] = v.x; QsT[d4 + 1][r] = v.y;
        QsT[d4 + 2][r] = v.z; QsT[d4 + 3][r] = v.w;
    }

    float m_i[4], l_i[4], Oacc[4][8];
#pragma unroll
    for (int i = 0; i < 4; i++) {
        m_i[i] = -1e30f;
        l_i[i] = 0.0f;
#pragma unroll
        for (int j = 0; j < 8; j++) Oacc[i][j] = 0.0f;
    }

    for (int t = 0; t < NSEQ / 32; t++) {
        __syncthreads();   // protect KsT/Vs/Ss from previous iteration's readers
        for (int i = tid; i < 32 * 16; i += 128) {
            const int c  = i >> 4;
            const int d4 = (i & 15) * 4;
            float4 kv = *(const float4*)&Kb[(t * 32 + c) * 64 + d4];
            KsT[d4 + 0][c] = kv.x; KsT[d4 + 1][c] = kv.y;
            KsT[d4 + 2][c] = kv.z; KsT[d4 + 3][c] = kv.w;
            float4 vv = *(const float4*)&Vb[(t * 32 + c) * 64 + d4];
            *(float4*)&Vs[c][d4] = vv;
        }
        __syncthreads();

        // S = Q K^T : per-thread 4 rows x 4 keys
        float S[4][4];
#pragma unroll
        for (int i = 0; i < 4; i++)
#pragma unroll
            for (int j = 0; j < 4; j++) S[i][j] = 0.0f;

#pragma unroll 8
        for (int k = 0; k < 64; k++) {
            float4 a  = *(float4*)&QsT[k][ty * 4];
            float4 bb = *(float4*)&KsT[k][tx * 4];
            float ar[4] = {a.x, a.y, a.z, a.w};
            float br[4] = {bb.x, bb.y, bb.z, bb.w};
#pragma unroll
            for (int i = 0; i < 4; i++)
#pragma unroll
                for (int j = 0; j < 4; j++) S[i][j] += ar[i] * br[j];
        }

        // online softmax per row (8 threads share a row-group via shfl width 8)
#pragma unroll
        for (int i = 0; i < 4; i++) {
            float mx = fmaxf(fmaxf(S[i][0], S[i][1]), fmaxf(S[i][2], S[i][3]));
#pragma unroll
            for (int msk = 4; msk >= 1; msk >>= 1)
                mx = fmaxf(mx, __shfl_xor_sync(0xffffffffu, mx, msk, 8));
            const float mnew = fmaxf(m_i[i], mx);
            const float corr = __expf(m_i[i] - mnew);
            m_i[i] = mnew;

            float p[4], rs = 0.0f;
#pragma unroll
            for (int j = 0; j < 4; j++) { p[j] = __expf(S[i][j] - mnew); rs += p[j]; }
#pragma unroll
            for (int msk = 4; msk >= 1; msk >>= 1)
                rs += __shfl_xor_sync(0xffffffffu, rs, msk, 8);
            l_i[i] = l_i[i] * corr + rs;

            const int r = ty * 4 + i;
            Ss[r][tx * 4 + 0] = p[0]; Ss[r][tx * 4 + 1] = p[1];
            Ss[r][tx * 4 + 2] = p[2]; Ss[r][tx * 4 + 3] = p[3];
#pragma unroll
            for (int jj = 0; jj < 8; jj++) Oacc[i][jj] *= corr;
        }
        __syncwarp();   // P tile is produced/consumed within each warp's row groups

        // O += P V : per-thread 4 rows x 8 dims (dims tx*8 .. tx*8+7)
#pragma unroll 4
        for (int j = 0; j < 32; j++) {
            float4 v0 = *(float4*)&Vs[j][tx * 8];
            float4 v1 = *(float4*)&Vs[j][tx * 8 + 4];
#pragma unroll
            for (int i = 0; i < 4; i++) {
                const float p = Ss[ty * 4 + i][j];
                Oacc[i][0] += p * v0.x; Oacc[i][1] += p * v0.y;
                Oacc[i][2] += p * v0.z; Oacc[i][3] += p * v0.w;
                Oacc[i][4] += p * v1.x; Oacc[i][5] += p * v1.y;
                Oacc[i][6] += p * v1.z; Oacc[i][7] += p * v1.w;
            }
        }
    }

    // finalize: O /= l, write to g_O [B, N, C] at column block h*64 + tx*8
#pragma unroll
    for (int i = 0; i < 4; i++) {
        const int n = qt * 64 + ty * 4 + i;
        const float inv = 1.0f / l_i[i];
        float* dst = &g_O[((size_t)(b * NSEQ + n)) * CDIM + h * 64 + tx * 8];
        float4 o0 = make_float4(Oacc[i][0] * inv, Oacc[i][1] * inv,
                                Oacc[i][2] * inv, Oacc[i][3] * inv);
        float4 o1 = make_float4(Oacc[i][4] * inv, Oacc[i][5] * inv,
                                Oacc[i][6] * inv, Oacc[i][7] * inv);
        *(float4*)&dst[0] = o0;
        *(float4*)&dst[4] = o1;
    }
}

// ---------------------------------------------------------------------------
// Kernel 3: output projection.  out[m, o] = sum_k g_O[m,k] * proj_w[o,k] + b[o]
// Same 128x128x8 tiling.  M = 8192, N = 768, K = 768.
// ---------------------------------------------------------------------------
__global__ __launch_bounds__(256) void proj_gemm_kernel(
    const float* __restrict__ w, const float* __restrict__ bias,
    float* __restrict__ out)
{
    __shared__ float As[8][128];
    __shared__ float Bs[8][128];

    const int m0 = blockIdx.y * 128;
    const int n0 = blockIdx.x * 128;
    const int tid = threadIdx.x;
    const int tx = tid & 15;
    const int ty = tid >> 4;
    const int lrow = tid & 127;
    const int lk   = (tid >> 7) * 4;

    float acc[8][8];
#pragma unroll
    for (int i = 0; i < 8; i++)
#pragma unroll
        for (int j = 0; j < 8; j++) acc[i][j] = 0.0f;

    for (int k0 = 0; k0 < 768; k0 += 8) {
        float4 av = *(const float4*)&g_O[(size_t)(m0 + lrow) * 768 + k0 + lk];
        float4 bv = *(const float4*)&w[(n0 + lrow) * 768 + k0 + lk];
        __syncthreads();
        As[lk + 0][lrow] = av.x; As[lk + 1][lrow] = av.y;
        As[lk + 2][lrow] = av.z; As[lk + 3][lrow] = av.w;
        Bs[lk + 0][lrow] = bv.x; Bs[lk + 1][lrow] = bv.y;
        Bs[lk + 2][lrow] = bv.z; Bs[lk + 3][lrow] = bv.w;
        __syncthreads();

#pragma unroll
        for (int k = 0; k < 8; k++) {
            float4 a0 = *(float4*)&As[k][ty * 8];
            float4 a1 = *(float4*)&As[k][ty * 8 + 4];
            float4 b0 = *(float4*)&Bs[k][tx * 8];
            float4 b1 = *(float4*)&Bs[k][tx * 8 + 4];
            float ar[8] = {a0.x, a0.y, a0.z, a0.w, a1.x, a1.y, a1.z, a1.w};
            float br[8] = {b0.x, b0.y, b0.z, b0.w, b1.x, b1.y, b1.z, b1.w};
#pragma unroll
            for (int i = 0; i < 8; i++)
#pragma unroll
                for (int j = 0; j < 8; j++) acc[i][j] += ar[i] * br[j];
        }
    }

#pragma unroll
    for (int i = 0; i < 8; i++) {
        const int m = m0 + ty * 8 + i;
#pragma unroll
        for (int j = 0; j < 8; j += 4) {
            const int o = n0 + tx * 8 + j;
            float4 bv = *(const float4*)&bias[o];
            float4 v = make_float4(acc[i][j + 0] + bv.x, acc[i][j + 1] + bv.y,
                                   acc[i][j + 2] + bv.z, acc[i][j + 3] + bv.w);
            *(float4*)&out[(size_t)m * 768 + o] = v;
        }
    }
}

// ---------------------------------------------------------------------------
extern "C" void kernel_launch(void* const* d_in, const int* in_sizes, int n_in,
                              void* d_out, int out_size)
{
    const float* x      = (const float*)d_in[0];
    const float* qkv_w  = (const float*)d_in[1];
    const float* proj_w = (const float*)d_in[2];
    const float* proj_b = (const float*)d_in[3];
    float* out = (float*)d_out;

    // QKV projection: M=8192 x N=2304 x K=768
    qkv_gemm_kernel<<<dim3(2304 / 128, MROWS / 128), 256>>>(x, qkv_w);

    // Flash attention: 16 q-tiles x 12 heads x 8 batches
    flash_attn_kernel<<<dim3(NSEQ / 64, NHEAD, BATCH), 128>>>();

    // Output projection: M=8192 x N=768 x K=768
    proj_gemm_kernel<<<dim3(768 / 128, MROWS / 128), 256>>>(proj_w, proj_b, out);
}

// round 2
// speedup vs baseline: 1.0047x; 1.0047x over previous
#include <cuda_runtime.h>
#include <math.h>

// Problem constants
#define BATCH 8
#define NSEQ  1024
#define CDIM  768
#define NHEAD 12
#define DHEAD 64
#define MROWS (BATCH * NSEQ)   // 8192
#define QK_SCALE 0.125f        // 64^-0.5

typedef unsigned long long u64;

// ---- packed f32x2 helpers (PTX-only on sm_103a; ptxas never auto-fuses) ----
__device__ __forceinline__ u64 fma2(u64 a, u64 b, u64 c) {
    u64 d; asm("fma.rn.f32x2 %0, %1, %2, %3;" : "=l"(d) : "l"(a), "l"(b), "l"(c));
    return d;
}
__device__ __forceinline__ u64 mul2(u64 a, u64 b) {
    u64 d; asm("mul.rn.f32x2 %0, %1, %2;" : "=l"(d) : "l"(a), "l"(b));
    return d;
}
__device__ __forceinline__ u64 dup2(float x) {
    u64 d; asm("mov.b64 %0, {%1, %1};" : "=l"(d) : "f"(x));
    return d;
}
__device__ __forceinline__ float2 unpack2(u64 v) {
    float2 r; asm("mov.b64 {%0, %1}, %2;" : "=f"(r.x), "=f"(r.y) : "l"(v));
    return r;
}

// Scratch: device globals (allocation-free kernel_launch)
__device__ float g_Q[BATCH * NHEAD * NSEQ * DHEAD];
__device__ float g_K[BATCH * NHEAD * NSEQ * DHEAD];
__device__ float g_V[BATCH * NHEAD * NSEQ * DHEAD];
__device__ float g_O[BATCH * NSEQ * CDIM];

// ---------------------------------------------------------------------------
// Kernel 1: QKV GEMM.  out[m, o] = sum_k x[m,k] * qkv_w[o,k]
// 128x128x8 tiles, 256 threads, 8x8 per-thread tile as 8x4 f32x2 pairs.
// Double-buffered smem: one __syncthreads per k-slab, LDG overlapped.
// ---------------------------------------------------------------------------
__global__ __launch_bounds__(256) void qkv_gemm_kernel(
    const float* __restrict__ x, const float* __restrict__ w)
{
    __shared__ __align__(16) float As[2][8][128];
    __shared__ __align__(16) float Bs[2][8][128];

    const int m0 = blockIdx.y * 128;
    const int n0 = blockIdx.x * 128;
    const int tid = threadIdx.x;
    const int tx = tid & 15;          // 0..15
    const int ty = tid >> 4;          // 0..15
    const int lrow = tid & 127;
    const int lk   = (tid >> 7) * 4;

    u64 acc[8][4];
#pragma unroll
    for (int i = 0; i < 8; i++)
#pragma unroll
        for (int jp = 0; jp < 4; jp++) acc[i][jp] = 0ull;

    // preload slab 0
    {
        float4 av = *(const float4*)&x[(m0 + lrow) * 768 + lk];
        float4 bv = *(const float4*)&w[(n0 + lrow) * 768 + lk];
        As[0][lk + 0][lrow] = av.x; As[0][lk + 1][lrow] = av.y;
        As[0][lk + 2][lrow] = av.z; As[0][lk + 3][lrow] = av.w;
        Bs[0][lk + 0][lrow] = bv.x; Bs[0][lk + 1][lrow] = bv.y;
        Bs[0][lk + 2][lrow] = bv.z; Bs[0][lk + 3][lrow] = bv.w;
    }
    __syncthreads();

    int buf = 0;
#pragma unroll 2
    for (int k0 = 0; k0 < 768; k0 += 8) {
        float4 av2, bv2;
        const bool more = (k0 + 8 < 768);
        if (more) {
            av2 = *(const float4*)&x[(m0 + lrow) * 768 + k0 + 8 + lk];
            bv2 = *(const float4*)&w[(n0 + lrow) * 768 + k0 + 8 + lk];
        }

#pragma unroll
        for (int k = 0; k < 8; k++) {
            float4 a0 = *(const float4*)&As[buf][k][ty * 8];
            float4 a1 = *(const float4*)&As[buf][k][ty * 8 + 4];
            ulonglong2 bp0 = *(const ulonglong2*)&Bs[buf][k][tx * 8];
            ulonglong2 bp1 = *(const ulonglong2*)&Bs[buf][k][tx * 8 + 4];
            u64 bq[4] = {bp0.x, bp0.y, bp1.x, bp1.y};
            float ar[8] = {a0.x, a0.y, a0.z, a0.w, a1.x, a1.y, a1.z, a1.w};
#pragma unroll
            for (int i = 0; i < 8; i++) {
                u64 ad = dup2(ar[i]);
#pragma unroll
                for (int jp = 0; jp < 4; jp++)
                    acc[i][jp] = fma2(ad, bq[jp], acc[i][jp]);
            }
        }

        if (more) {
            const int nb = buf ^ 1;
            As[nb][lk + 0][lrow] = av2.x; As[nb][lk + 1][lrow] = av2.y;
            As[nb][lk + 2][lrow] = av2.z; As[nb][lk + 3][lrow] = av2.w;
            Bs[nb][lk + 0][lrow] = bv2.x; Bs[nb][lk + 1][lrow] = bv2.y;
            Bs[nb][lk + 2][lrow] = bv2.z; Bs[nb][lk + 3][lrow] = bv2.w;
            __syncthreads();
            buf = nb;
        }
    }

    // epilogue: scatter into Q/K/V  [B,H,N,D]
#pragma unroll
    for (int i = 0; i < 8; i++) {
        const int m = m0 + ty * 8 + i;
        const int b = m >> 10;
        const int n = m & 1023;
#pragma unroll
        for (int jp = 0; jp < 4; jp++) {
            float2 v2 = unpack2(acc[i][jp]);
            float vv[2] = {v2.x, v2.y};
#pragma unroll
            for (int u = 0; u < 2; u++) {
                const int o = n0 + tx * 8 + jp * 2 + u;
                const int which = o / 768;
                const int r = o - which * 768;
                const int h = r >> 6;
                const int d = r & 63;
                const int idx = ((b * NHEAD + h) * NSEQ + n) * DHEAD + d;
                const float v = vv[u];
                if (which == 0)      g_Q[idx] = v * QK_SCALE;
                else if (which == 1) g_K[idx] = v;
                else                 g_V[idx] = v;
            }
        }
    }
}

// ---------------------------------------------------------------------------
// Kernel 2: flash attention.  One block per (q-tile of 64 rows, head, batch).
// 128 threads: tx 0..7, ty 0..15.  Key tiles of 32, online softmax.
// S and O accumulation in packed f32x2.
// ---------------------------------------------------------------------------
__global__ __launch_bounds__(128) void flash_attn_kernel()
{
    __shared__ __align__(16) float QsT[64][68];   // [d][row]
    __shared__ __align__(16) float KsT[64][40];   // [d][key]  (16B row stride mult.)
    __shared__ __align__(16) float Vs[32][68];    // [key][d]
    __shared__ float Ss[64][36];                  // [row][key] (P tile)

    const int qt = blockIdx.x;
    const int h  = blockIdx.y;
    const int b  = blockIdx.z;
    const int tid = threadIdx.x;
    const int tx = tid & 7;
    const int ty = tid >> 3;

    const float* Qb = g_Q + ((b * NHEAD + h) * NSEQ + qt * 64) * DHEAD;
    const float* Kb = g_K + ((size_t)(b * NHEAD + h) * NSEQ) * DHEAD;
    const float* Vb = g_V + ((size_t)(b * NHEAD + h) * NSEQ) * DHEAD;

    for (int i = tid; i < 64 * 16; i += 128) {
        const int r  = i >> 4;
        const int d4 = (i & 15) * 4;
        float4 v = *(const float4*)&Qb[r * 64 + d4];
        QsT[d4 + 0][r] = v.x; QsT[d4 + 1][r] = v.y;
        QsT[d4 + 2][r] = v.z; QsT[d4 + 3][r] = v.w;
    }

    float m_i[4], l_i[4];
    u64 Op[4][4];
#pragma unroll
    for (int i = 0; i < 4; i++) {
        m_i[i] = -1e30f; l_i[i] = 0.0f;
#pragma unroll
        for (int jp = 0; jp < 4; jp++) Op[i][jp] = 0ull;
    }

    for (int t = 0; t < NSEQ / 32; t++) {
        __syncthreads();
        for (int i = tid; i < 32 * 16; i += 128) {
            const int c  = i >> 4;
            const int d4 = (i & 15) * 4;
            float4 kv = *(const float4*)&Kb[(t * 32 + c) * 64 + d4];
            KsT[d4 + 0][c] = kv.x; KsT[d4 + 1][c] = kv.y;
            KsT[d4 + 2][c] = kv.z; KsT[d4 + 3][c] = kv.w;
            float4 vv = *(const float4*)&Vb[(t * 32 + c) * 64 + d4];
            *(float4*)&Vs[c][d4] = vv;
        }
        __syncthreads();

        // S = Q K^T : 4 rows x 4 keys per thread, keys as f32x2 pairs
        u64 Sp[4][2];
#pragma unroll
        for (int i = 0; i < 4; i++) { Sp[i][0] = 0ull; Sp[i][1] = 0ull; }

#pragma unroll 8
        for (int k = 0; k < 64; k++) {
            float4 a = *(const float4*)&QsT[k][ty * 4];
            ulonglong2 bp = *(const ulonglong2*)&KsT[k][tx * 4];
            float ar[4] = {a.x, a.y, a.z, a.w};
#pragma unroll
            for (int i = 0; i < 4; i++) {
                u64 ad = dup2(ar[i]);
                Sp[i][0] = fma2(ad, bp.x, Sp[i][0]);
                Sp[i][1] = fma2(ad, bp.y, Sp[i][1]);
            }
        }

        // online softmax per row (8 threads per row share via shfl width 8)
#pragma unroll
        for (int i = 0; i < 4; i++) {
            float2 s01 = unpack2(Sp[i][0]);
            float2 s23 = unpack2(Sp[i][1]);
            float S0 = s01.x, S1 = s01.y, S2 = s23.x, S3 = s23.y;
            float mx = fmaxf(fmaxf(S0, S1), fmaxf(S2, S3));
#pragma unroll
            for (int msk = 4; msk >= 1; msk >>= 1)
                mx = fmaxf(mx, __shfl_xor_sync(0xffffffffu, mx, msk, 8));
            const float mnew = fmaxf(m_i[i], mx);
            const float corr = __expf(m_i[i] - mnew);
            m_i[i] = mnew;

            float p0 = __expf(S0 - mnew), p1 = __expf(S1 - mnew);
            float p2 = __expf(S2 - mnew), p3 = __expf(S3 - mnew);
            float rs = p0 + p1 + p2 + p3;
#pragma unroll
            for (int msk = 4; msk >= 1; msk >>= 1)
                rs += __shfl_xor_sync(0xffffffffu, rs, msk, 8);
            l_i[i] = l_i[i] * corr + rs;

            const int r = ty * 4 + i;
            Ss[r][tx * 4 + 0] = p0; Ss[r][tx * 4 + 1] = p1;
            Ss[r][tx * 4 + 2] = p2; Ss[r][tx * 4 + 3] = p3;

            const u64 corr2 = dup2(corr);
#pragma unroll
            for (int jp = 0; jp < 4; jp++) Op[i][jp] = mul2(Op[i][jp], corr2);
        }
        __syncwarp();

        // O += P V : 4 rows x 8 dims per thread, dims as f32x2 pairs
#pragma unroll 4
        for (int j = 0; j < 32; j++) {
            ulonglong2 v0 = *(const ulonglong2*)&Vs[j][tx * 8];
            ulonglong2 v1 = *(const ulonglong2*)&Vs[j][tx * 8 + 4];
#pragma unroll
            for (int i = 0; i < 4; i++) {
                const u64 pd = dup2(Ss[ty * 4 + i][j]);
                Op[i][0] = fma2(pd, v0.x, Op[i][0]);
                Op[i][1] = fma2(pd, v0.y, Op[i][1]);
                Op[i][2] = fma2(pd, v1.x, Op[i][2]);
                Op[i][3] = fma2(pd, v1.y, Op[i][3]);
            }
        }
    }

    // finalize: O /= l, write to g_O [B, N, C]
#pragma unroll
    for (int i = 0; i < 4; i++) {
        const int n = qt * 64 + ty * 4 + i;
        const float inv = 1.0f / l_i[i];
        float* dst = &g_O[((size_t)(b * NSEQ + n)) * CDIM + h * 64 + tx * 8];
        float2 o0 = unpack2(Op[i][0]);
        float2 o1 = unpack2(Op[i][1]);
        float2 o2 = unpack2(Op[i][2]);
        float2 o3 = unpack2(Op[i][3]);
        float4 w0 = make_float4(o0.x * inv, o0.y * inv, o1.x * inv, o1.y * inv);
        float4 w1 = make_float4(o2.x * inv, o2.y * inv, o3.x * inv, o3.y * inv);
        *(float4*)&dst[0] = w0;
        *(float4*)&dst[4] = w1;
    }
}

// ---------------------------------------------------------------------------
// Kernel 3: output projection.  out[m, o] = sum_k g_O[m,k] * proj_w[o,k] + b[o]
// Same structure as kernel 1 (double buffer + f32x2).
// ---------------------------------------------------------------------------
__global__ __launch_bounds__(256) void proj_gemm_kernel(
    const float* __restrict__ w, const float* __restrict__ bias,
    float* __restrict__ out)
{
    __shared__ __align__(16) float As[2][8][128];
    __shared__ __align__(16) float Bs[2][8][128];

    const int m0 = blockIdx.y * 128;
    const int n0 = blockIdx.x * 128;
    const int tid = threadIdx.x;
    const int tx = tid & 15;
    const int ty = tid >> 4;
    const int lrow = tid & 127;
    const int lk   = (tid >> 7) * 4;

    u64 acc[8][4];
#pragma unroll
    for (int i = 0; i < 8; i++)
#pragma unroll
        for (int jp = 0; jp < 4; jp++) acc[i][jp] = 0ull;

    {
        float4 av = *(const float4*)&g_O[(size_t)(m0 + lrow) * 768 + lk];
        float4 bv = *(const float4*)&w[(n0 + lrow) * 768 + lk];
        As[0][lk + 0][lrow] = av.x; As[0][lk + 1][lrow] = av.y;
        As[0][lk + 2][lrow] = av.z; As[0][lk + 3][lrow] = av.w;
        Bs[0][lk + 0][lrow] = bv.x; Bs[0][lk + 1][lrow] = bv.y;
        Bs[0][lk + 2][lrow] = bv.z; Bs[0][lk + 3][lrow] = bv.w;
    }
    __syncthreads();

    int buf = 0;
#pragma unroll 2
    for (int k0 = 0; k0 < 768; k0 += 8) {
        float4 av2, bv2;
        const bool more = (k0 + 8 < 768);
        if (more) {
            av2 = *(const float4*)&g_O[(size_t)(m0 + lrow) * 768 + k0 + 8 + lk];
            bv2 = *(const float4*)&w[(n0 + lrow) * 768 + k0 + 8 + lk];
        }

#pragma unroll
        for (int k = 0; k < 8; k++) {
            float4 a0 = *(const float4*)&As[buf][k][ty * 8];
            float4 a1 = *(const float4*)&As[buf][k][ty * 8 + 4];
            ulonglong2 bp0 = *(const ulonglong2*)&Bs[buf][k][tx * 8];
            ulonglong2 bp1 = *(const ulonglong2*)&Bs[buf][k][tx * 8 + 4];
            u64 bq[4] = {bp0.x, bp0.y, bp1.x, bp1.y};
            float ar[8] = {a0.x, a0.y, a0.z, a0.w, a1.x, a1.y, a1.z, a1.w};
#pragma unroll
            for (int i = 0; i < 8; i++) {
                u64 ad = dup2(ar[i]);
#pragma unroll
                for (int jp = 0; jp < 4; jp++)
                    acc[i][jp] = fma2(ad, bq[jp], acc[i][jp]);
            }
        }

        if (more) {
            const int nb = buf ^ 1;
            As[nb][lk + 0][lrow] = av2.x; As[nb][lk + 1][lrow] = av2.y;
            As[nb][lk + 2][lrow] = av2.z; As[nb][lk + 3][lrow] = av2.w;
            Bs[nb][lk + 0][lrow] = bv2.x; Bs[nb][lk + 1][lrow] = bv2.y;
            Bs[nb][lk + 2][lrow] = bv2.z; Bs[nb][lk + 3][lrow] = bv2.w;
            __syncthreads();
            buf = nb;
        }
    }

#pragma unroll
    for (int i = 0; i < 8; i++) {
        const int m = m0 + ty * 8 + i;
#pragma unroll
        for (int jp = 0; jp < 4; jp += 2) {
            const int o = n0 + tx * 8 + jp * 2;
            float4 bv = *(const float4*)&bias[o];
            float2 v0 = unpack2(acc[i][jp]);
            float2 v1 = unpack2(acc[i][jp + 1]);
            float4 v = make_float4(v0.x + bv.x, v0.y + bv.y,
                                   v1.x + bv.z, v1.y + bv.w);
            *(float4*)&out[(size_t)m * 768 + o] = v;
        }
    }
}

// ---------------------------------------------------------------------------
extern "C" void kernel_launch(void* const* d_in, const int* in_sizes, int n_in,
                              void* d_out, int out_size)
{
    const float* x      = (const float*)d_in[0];
    const float* qkv_w  = (const float*)d_in[1];
    const float* proj_w = (const float*)d_in[2];
    const float* proj_b = (const float*)d_in[3];
    float* out = (float*)d_out;

    qkv_gemm_kernel<<<dim3(2304 / 128, MROWS / 128), 256>>>(x, qkv_w);
    flash_attn_kernel<<<dim3(NSEQ / 64, NHEAD, BATCH), 128>>>();
    proj_gemm_kernel<<<dim3(768 / 128, MROWS / 128), 256>>>(proj_w, proj_b, out);
}

// round 4
// speedup vs baseline: 1.5273x; 1.5202x over previous
#include <cuda_runtime.h>
#include <cuda_bf16.h>
#include <cstdint>
#include <math.h>

#define BATCH 8
#define NSEQ  1024
#define CDIM  768
#define NHEAD 12
#define DHEAD 64
#define MROWS 8192
#define KDIM  768
#define QK_SCALE 0.125f

typedef unsigned long long u64;
typedef unsigned int u32;

// ---------------------------------------------------------------------------
// scratch globals (allocation-free)
// ---------------------------------------------------------------------------
__device__ __nv_bfloat16 g_xhi[MROWS * CDIM],  g_xlo[MROWS * CDIM];
__device__ __nv_bfloat16 g_qwhi[3 * CDIM * CDIM], g_qwlo[3 * CDIM * CDIM];
__device__ __nv_bfloat16 g_pwhi[CDIM * CDIM], g_pwlo[CDIM * CDIM];
__device__ float g_Q[BATCH * NHEAD * NSEQ * DHEAD];
__device__ float g_K[BATCH * NHEAD * NSEQ * DHEAD];
__device__ float g_V[BATCH * NHEAD * NSEQ * DHEAD];
__device__ __nv_bfloat16 g_Ohi[MROWS * CDIM], g_Olo[MROWS * CDIM];

// ---------------------------------------------------------------------------
// PTX helpers — sm_80-era instruction set only (valid under compute_103)
// ---------------------------------------------------------------------------
__device__ __forceinline__ u32 smem_u32(const void* p) {
    u32 a;
    asm("{ .reg .u64 t; cvta.to.shared.u64 t, %1; cvt.u32.u64 %0, t; }"
        : "=r"(a) : "l"(p));
    return a;
}

#define CP_ASYNC16(dst, src) \
    asm volatile("cp.async.cg.shared.global [%0], [%1], 16;" \
        :: "r"(dst), "l"(src) : "memory")
#define CP_COMMIT() asm volatile("cp.async.commit_group;" ::: "memory")
#define CP_WAIT1()  asm volatile("cp.async.wait_group 1;" ::: "memory")

__device__ __forceinline__ void ldmx4(u32& r0, u32& r1, u32& r2, u32& r3, u32 addr) {
    asm volatile("ldmatrix.sync.aligned.m8n8.x4.shared.b16 {%0,%1,%2,%3}, [%4];"
        : "=r"(r0), "=r"(r1), "=r"(r2), "=r"(r3) : "r"(addr));
}

__device__ __forceinline__ void mma16816(float* c, const u32* a, const u32* b) {
    asm volatile(
        "mma.sync.aligned.m16n8k16.row.col.f32.bf16.bf16.f32 "
        "{%0,%1,%2,%3}, {%4,%5,%6,%7}, {%8,%9}, {%0,%1,%2,%3};"
        : "+f"(c[0]), "+f"(c[1]), "+f"(c[2]), "+f"(c[3])
        : "r"(a[0]), "r"(a[1]), "r"(a[2]), "r"(a[3]), "r"(b[0]), "r"(b[1]));
}

// ---------------------------------------------------------------------------
// Kernel 0: fp32 -> bf16 hi/lo split. which: 0=x, 1=qkv_w, 2=proj_w
// ---------------------------------------------------------------------------
__global__ __launch_bounds__(256) void cvt_split_kernel(
    const float* __restrict__ src, int n, int which)
{
    int i = (blockIdx.x * 256 + threadIdx.x) * 4;
    if (i >= n) return;
    float4 v = *(const float4*)(src + i);
    __nv_bfloat16 h0 = __float2bfloat16(v.x);
    __nv_bfloat16 h1 = __float2bfloat16(v.y);
    __nv_bfloat16 h2 = __float2bfloat16(v.z);
    __nv_bfloat16 h3 = __float2bfloat16(v.w);
    __nv_bfloat16 l0 = __float2bfloat16(v.x - __bfloat162float(h0));
    __nv_bfloat16 l1 = __float2bfloat16(v.y - __bfloat162float(h1));
    __nv_bfloat16 l2 = __float2bfloat16(v.z - __bfloat162float(h2));
    __nv_bfloat16 l3 = __float2bfloat16(v.w - __bfloat162float(h3));
    __nv_bfloat16* hid = (which == 0) ? g_xhi : (which == 1) ? g_qwhi : g_pwhi;
    __nv_bfloat16* lod = (which == 0) ? g_xlo : (which == 1) ? g_qwlo : g_pwlo;
    __nv_bfloat162 hh0; hh0.x = h0; hh0.y = h1;
    __nv_bfloat162 hh1; hh1.x = h2; hh1.y = h3;
    __nv_bfloat162 ll0; ll0.x = l0; ll0.y = l1;
    __nv_bfloat162 ll1; ll1.x = l2; ll1.y = l3;
    *(__nv_bfloat162*)(hid + i)     = hh0;
    *(__nv_bfloat162*)(hid + i + 2) = hh1;
    *(__nv_bfloat162*)(lod + i)     = ll0;
    *(__nv_bfloat162*)(lod + i + 2) = ll1;
}

// ---------------------------------------------------------------------------
// Kernel 1: mma.sync split-bf16 GEMM.  C[m,o] = sum_k A[m,k] * B[o,k]
//   C = Ahi*Bhi + Ahi*Blo + Alo*Bhi  (fp32 accum)
// Block 128x128, 8 warps of 64x32, K-slab 32 bf16, 2-stage cp.async pipeline.
// smem per stage: 4 arrays (Ahi,Alo,Bhi,Blo) of 128 rows x 32 bf16, stride 80B.
// mode 0: A=x, B=qkv_w; scatter fp32 Q(*scale)/K/V.   mode 1: proj (+bias).
// ---------------------------------------------------------------------------
#define ARR_BYTES   10240           // 128 * 80
#define STAGE_BYTES 40960           // 4 * ARR_BYTES
#define SMEM_DYN    81920           // 2 stages
#define NSLAB       24              // 768 / 32

__global__ __launch_bounds__(256, 2) void gemm_tc_kernel(
    int mode, const float* __restrict__ bias, float* __restrict__ out)
{
    extern __shared__ char smem_raw[];
    const u32 smem_base = smem_u32(smem_raw);

    const int tid = threadIdx.x;
    const int wid = tid >> 5;
    const int lane = tid & 31;
    const int warp_m = wid >> 2;      // 0..1
    const int warp_n = wid & 3;       // 0..3
    const int m0 = blockIdx.y * 128;
    const int n0 = blockIdx.x * 128;

    const __nv_bfloat16 *Ahi, *Alo, *Bhi, *Blo;
    if (mode == 0) { Ahi = g_xhi; Alo = g_xlo; Bhi = g_qwhi; Blo = g_qwlo; }
    else           { Ahi = g_Ohi; Alo = g_Olo; Bhi = g_pwhi; Blo = g_pwlo; }

    // slab loader: 2048 x 16B cp.async (8 per thread)
    auto load_slab = [&](int st, int kele) {
        const u32 stb = smem_base + st * STAGE_BYTES;
#pragma unroll
        for (int e = tid; e < 2048; e += 256) {
            const int arr = e >> 9;          // 0:Ahi 1:Alo 2:Bhi 3:Blo
            const int i = e & 511;
            const int row = i >> 2, ch = i & 3;
            const __nv_bfloat16* base =
                (arr == 0) ? Ahi : (arr == 1) ? Alo : (arr == 2) ? Bhi : Blo;
            const int grow = ((arr < 2) ? m0 : n0) + row;
            const __nv_bfloat16* src = base + (size_t)grow * KDIM + kele + ch * 8;
            const u32 dst = stb + arr * ARR_BYTES + row * 80 + ch * 16;
            CP_ASYNC16(dst, src);
        }
    };

    float C[4][4][4];
#pragma unroll
    for (int i = 0; i < 4; i++)
#pragma unroll
        for (int j = 0; j < 4; j++)
#pragma unroll
            for (int r = 0; r < 4; r++) C[i][j][r] = 0.0f;

    load_slab(0, 0);  CP_COMMIT();
    load_slab(1, 32); CP_COMMIT();

    // fragment address components (per lane, fixed)
    const u32 a_row = warp_m * 64 + (lane & 15);
    const u32 a_colh = ((lane >> 4) & 1) * 16;        // bytes (8 bf16)
    const u32 b_row = warp_n * 32 + (lane & 7) + ((lane & 16) >> 1);
    const u32 b_colh = ((lane >> 3) & 1) * 16;

    for (int s = 0; s < NSLAB; s++) {
        CP_WAIT1();
        __syncthreads();
        const u32 stb = smem_base + (s & 1) * STAGE_BYTES;

#pragma unroll
        for (int kk = 0; kk < 2; kk++) {
            const u32 k0b = kk * 32;   // 16 bf16 = 32 bytes

            // B fragments (hi & lo): 4 n-subtiles x 2 regs
            u32 Bh[4][2], Bl[4][2];
#pragma unroll
            for (int np = 0; np < 2; np++) {
                const u32 badr = stb + 2 * ARR_BYTES +
                                 (b_row + np * 16) * 80 + k0b + b_colh;
                u32 r0, r1, r2, r3;
                ldmx4(r0, r1, r2, r3, badr);
                Bh[np * 2][0] = r0; Bh[np * 2][1] = r1;
                Bh[np * 2 + 1][0] = r2; Bh[np * 2 + 1][1] = r3;
                ldmx4(r0, r1, r2, r3, badr + ARR_BYTES);
                Bl[np * 2][0] = r0; Bl[np * 2][1] = r1;
                Bl[np * 2 + 1][0] = r2; Bl[np * 2 + 1][1] = r3;
            }

            // A-hi fragments, then hh + hl MMAs
            u32 A[4][4];
#pragma unroll
            for (int ms = 0; ms < 4; ms++) {
                const u32 aadr = stb + (a_row + ms * 16) * 80 + k0b + a_colh;
                ldmx4(A[ms][0], A[ms][1], A[ms][2], A[ms][3], aadr);
            }
#pragma unroll
            for (int ms = 0; ms < 4; ms++)
#pragma unroll
                for (int ns = 0; ns < 4; ns++) {
                    mma16816(C[ms][ns], A[ms], Bh[ns]);
                    mma16816(C[ms][ns], A[ms], Bl[ns]);
                }

            // A-lo fragments (reuse regs), then lh MMAs
#pragma unroll
            for (int ms = 0; ms < 4; ms++) {
                const u32 aadr = stb + ARR_BYTES + (a_row + ms * 16) * 80 + k0b + a_colh;
                ldmx4(A[ms][0], A[ms][1], A[ms][2], A[ms][3], aadr);
            }
#pragma unroll
            for (int ms = 0; ms < 4; ms++)
#pragma unroll
                for (int ns = 0; ns < 4; ns++)
                    mma16816(C[ms][ns], A[ms], Bh[ns]);
        }

        __syncthreads();
        if (s + 2 < NSLAB) load_slab(s & 1, (s + 2) * 32);
        CP_COMMIT();   // commit every iter (possibly empty) to keep group count
    }

    // epilogue: C fragment -> global
    const int r_in = lane >> 2;           // 0..7
    const int c_in = (lane & 3) * 2;      // 0,2,4,6
#pragma unroll
    for (int ms = 0; ms < 4; ms++) {
#pragma unroll
        for (int ns = 0; ns < 4; ns++) {
            const int col = n0 + warp_n * 32 + ns * 8 + c_in;
#pragma unroll
            for (int half = 0; half < 2; half++) {
                const int row = m0 + warp_m * 64 + ms * 16 + r_in + half * 8;
                const float v0 = C[ms][ns][half * 2 + 0];
                const float v1 = C[ms][ns][half * 2 + 1];
                if (mode == 0) {
                    const int which = col / 768;
                    const int rem = col - which * 768;
                    const int h = rem >> 6, d = rem & 63;
                    const int b = row >> 10, n = row & 1023;
                    float* base = (which == 0) ? g_Q : (which == 1) ? g_K : g_V;
                    float* dst = base + ((size_t)(b * NHEAD + h) * NSEQ + n) * DHEAD + d;
                    const float sc = (which == 0) ? QK_SCALE : 1.0f;
                    float2 w = make_float2(v0 * sc, v1 * sc);
                    *(float2*)dst = w;
                } else {
                    const float2 bb = *(const float2*)(bias + col);
                    float2 w = make_float2(v0 + bb.x, v1 + bb.y);
                    *(float2*)(out + (size_t)row * 768 + col) = w;
                }
            }
        }
    }
}

// ---------------------------------------------------------------------------
// Kernel 2: flash attention (SIMT fp32, packed f32x2).
// Output split to bf16 hi/lo into g_Ohi/g_Olo for the proj GEMM.
// ---------------------------------------------------------------------------
__device__ __forceinline__ u64 fma2(u64 a, u64 b, u64 c) {
    u64 d; asm("fma.rn.f32x2 %0, %1, %2, %3;" : "=l"(d) : "l"(a), "l"(b), "l"(c));
    return d;
}
__device__ __forceinline__ u64 mul2(u64 a, u64 b) {
    u64 d; asm("mul.rn.f32x2 %0, %1, %2;" : "=l"(d) : "l"(a), "l"(b));
    return d;
}
__device__ __forceinline__ u64 dup2(float x) {
    u64 d; asm("mov.b64 %0, {%1, %1};" : "=l"(d) : "f"(x));
    return d;
}
__device__ __forceinline__ float2 unpack2(u64 v) {
    float2 r; asm("mov.b64 {%0, %1}, %2;" : "=f"(r.x), "=f"(r.y) : "l"(v));
    return r;
}

__global__ __launch_bounds__(128) void flash_attn_kernel()
{
    __shared__ __align__(16) float QsT[64][68];
    __shared__ __align__(16) float KsT[64][40];
    __shared__ __align__(16) float Vs[32][68];
    __shared__ float Ss[64][36];

    const int qt = blockIdx.x;
    const int h  = blockIdx.y;
    const int b  = blockIdx.z;
    const int tid = threadIdx.x;
    const int tx = tid & 7;
    const int ty = tid >> 3;

    const float* Qb = g_Q + ((b * NHEAD + h) * NSEQ + qt * 64) * DHEAD;
    const float* Kb = g_K + ((size_t)(b * NHEAD + h) * NSEQ) * DHEAD;
    const float* Vb = g_V + ((size_t)(b * NHEAD + h) * NSEQ) * DHEAD;

    for (int i = tid; i < 64 * 16; i += 128) {
        const int r  = i >> 4;
        const int d4 = (i & 15) * 4;
        float4 v = *(const float4*)&Qb[r * 64 + d4];
        QsT[d4 + 0][r] = v.x; QsT[d4 + 1][r] = v.y;
        QsT[d4 + 2][r] = v.z; QsT[d4 + 3][r] = v.w;
    }

    float m_i[4], l_i[4];
    u64 Op[4][4];
#pragma unroll
    for (int i = 0; i < 4; i++) {
        m_i[i] = -1e30f; l_i[i] = 0.0f;
#pragma unroll
        for (int jp = 0; jp < 4; jp++) Op[i][jp] = 0ull;
    }

    for (int t = 0; t < NSEQ / 32; t++) {
        __syncthreads();
        for (int i = tid; i < 32 * 16; i += 128) {
            const int c  = i >> 4;
            const int d4 = (i & 15) * 4;
            float4 kv = *(const float4*)&Kb[(t * 32 + c) * 64 + d4];
            KsT[d4 + 0][c] = kv.x; KsT[d4 + 1][c] = kv.y;
            KsT[d4 + 2][c] = kv.z; KsT[d4 + 3][c] = kv.w;
            float4 vv = *(const float4*)&Vb[(t * 32 + c) * 64 + d4];
            *(float4*)&Vs[c][d4] = vv;
        }
        __syncthreads();

        u64 Sp[4][2];
#pragma unroll
        for (int i = 0; i < 4; i++) { Sp[i][0] = 0ull; Sp[i][1] = 0ull; }

#pragma unroll 8
        for (int k = 0; k < 64; k++) {
            float4 a = *(const float4*)&QsT[k][ty * 4];
            ulonglong2 bp = *(const ulonglong2*)&KsT[k][tx * 4];
            float ar[4] = {a.x, a.y, a.z, a.w};
#pragma unroll
            for (int i = 0; i < 4; i++) {
                u64 ad = dup2(ar[i]);
                Sp[i][0] = fma2(ad, bp.x, Sp[i][0]);
                Sp[i][1] = fma2(ad, bp.y, Sp[i][1]);
            }
        }

#pragma unroll
        for (int i = 0; i < 4; i++) {
            float2 s01 = unpack2(Sp[i][0]);
            float2 s23 = unpack2(Sp[i][1]);
            float S0 = s01.x, S1 = s01.y, S2 = s23.x, S3 = s23.y;
            float mx = fmaxf(fmaxf(S0, S1), fmaxf(S2, S3));
#pragma unroll
            for (int msk = 4; msk >= 1; msk >>= 1)
                mx = fmaxf(mx, __shfl_xor_sync(0xffffffffu, mx, msk, 8));
            const float mnew = fmaxf(m_i[i], mx);
            const float corr = __expf(m_i[i] - mnew);
            m_i[i] = mnew;

            float p0 = __expf(S0 - mnew), p1 = __expf(S1 - mnew);
            float p2 = __expf(S2 - mnew), p3 = __expf(S3 - mnew);
            float rs = p0 + p1 + p2 + p3;
#pragma unroll
            for (int msk = 4; msk >= 1; msk >>= 1)
                rs += __shfl_xor_sync(0xffffffffu, rs, msk, 8);
            l_i[i] = l_i[i] * corr + rs;

            const int r = ty * 4 + i;
            Ss[r][tx * 4 + 0] = p0; Ss[r][tx * 4 + 1] = p1;
            Ss[r][tx * 4 + 2] = p2; Ss[r][tx * 4 + 3] = p3;

            const u64 corr2 = dup2(corr);
#pragma unroll
            for (int jp = 0; jp < 4; jp++) Op[i][jp] = mul2(Op[i][jp], corr2);
        }
        __syncwarp();

#pragma unroll 4
        for (int j = 0; j < 32; j++) {
            ulonglong2 v0 = *(const ulonglong2*)&Vs[j][tx * 8];
            ulonglong2 v1 = *(const ulonglong2*)&Vs[j][tx * 8 + 4];
#pragma unroll
            for (int i = 0; i < 4; i++) {
                const u64 pd = dup2(Ss[ty * 4 + i][j]);
                Op[i][0] = fma2(pd, v0.x, Op[i][0]);
                Op[i][1] = fma2(pd, v0.y, Op[i][1]);
                Op[i][2] = fma2(pd, v1.x, Op[i][2]);
                Op[i][3] = fma2(pd, v1.y, Op[i][3]);
            }
        }
    }

#pragma unroll
    for (int i = 0; i < 4; i++) {
        const int n = qt * 64 + ty * 4 + i;
        const float inv = 1.0f / l_i[i];
        const size_t base = (size_t)(b * NSEQ + n) * CDIM + h * 64 + tx * 8;
        float vals[8];
        float2 o0 = unpack2(Op[i][0]);
        float2 o1 = unpack2(Op[i][1]);
        float2 o2 = unpack2(Op[i][2]);
        float2 o3 = unpack2(Op[i][3]);
        vals[0] = o0.x * inv; vals[1] = o0.y * inv;
        vals[2] = o1.x * inv; vals[3] = o1.y * inv;
        vals[4] = o2.x * inv; vals[5] = o2.y * inv;
        vals[6] = o3.x * inv; vals[7] = o3.y * inv;
        union { __nv_bfloat16 h[8]; uint4 u; } uh, ul;
#pragma unroll
        for (int j = 0; j < 8; j++) {
            uh.h[j] = __float2bfloat16(vals[j]);
            ul.h[j] = __float2bfloat16(vals[j] - __bfloat162float(uh.h[j]));
        }
        *(uint4*)(g_Ohi + base) = uh.u;
        *(uint4*)(g_Olo + base) = ul.u;
    }
}

// ---------------------------------------------------------------------------
extern "C" void kernel_launch(void* const* d_in, const int* in_sizes, int n_in,
                              void* d_out, int out_size)
{
    const float* x      = (const float*)d_in[0];
    const float* qkv_w  = (const float*)d_in[1];
    const float* proj_w = (const float*)d_in[2];
    const float* proj_b = (const float*)d_in[3];
    float* out = (float*)d_out;

    cudaFuncSetAttribute(gemm_tc_kernel,
                         cudaFuncAttributeMaxDynamicSharedMemorySize, SMEM_DYN);

    cvt_split_kernel<<<(MROWS * CDIM) / 1024, 256>>>(x, MROWS * CDIM, 0);
    cvt_split_kernel<<<(3 * CDIM * CDIM) / 1024, 256>>>(qkv_w, 3 * CDIM * CDIM, 1);
    cvt_split_kernel<<<(CDIM * CDIM) / 1024, 256>>>(proj_w, CDIM * CDIM, 2);

    // QKV projection: M=8192 x N=2304 x K=768 -> fp32 Q(*scale)/K/V
    gemm_tc_kernel<<<dim3(2304 / 128, MROWS / 128), 256, SMEM_DYN>>>(0, nullptr, nullptr);

    // Flash attention (fp32 SIMT) -> bf16 hi/lo attention output
    flash_attn_kernel<<<dim3(NSEQ / 64, NHEAD, BATCH), 128>>>();

    // Output projection: M=8192 x N=768 x K=768 (+bias) -> d_out
    gemm_tc_kernel<<<dim3(768 / 128, MROWS / 128), 256, SMEM_DYN>>>(1, proj_b, out);
}

// round 5
// speedup vs baseline: 3.4352x; 2.2492x over previous
#include <cuda_runtime.h>
#include <cuda_bf16.h>
#include <cstdint>
#include <math.h>

#define BATCH 8
#define NSEQ  1024
#define CDIM  768
#define NHEAD 12
#define DHEAD 64
#define MROWS 8192
#define KDIM  768
#define QK_SCALE 0.125f

typedef unsigned long long u64;
typedef unsigned int u32;

// ---------------------------------------------------------------------------
// scratch globals (allocation-free)
// ---------------------------------------------------------------------------
__device__ __nv_bfloat16 g_xhi[MROWS * CDIM],  g_xlo[MROWS * CDIM];
__device__ __nv_bfloat16 g_qwhi[3 * CDIM * CDIM], g_qwlo[3 * CDIM * CDIM];
__device__ __nv_bfloat16 g_pwhi[CDIM * CDIM], g_pwlo[CDIM * CDIM];
// Q/K: [B,H,N,D] bf16 hi/lo (Q pre-scaled).  V: transposed [B,H,D,N] hi/lo.
__device__ __nv_bfloat16 g_Qhi[BATCH * NHEAD * NSEQ * DHEAD], g_Qlo[BATCH * NHEAD * NSEQ * DHEAD];
__device__ __nv_bfloat16 g_Khi[BATCH * NHEAD * NSEQ * DHEAD], g_Klo[BATCH * NHEAD * NSEQ * DHEAD];
__device__ __nv_bfloat16 g_Vthi[BATCH * NHEAD * DHEAD * NSEQ], g_Vtlo[BATCH * NHEAD * DHEAD * NSEQ];
__device__ __nv_bfloat16 g_Ohi[MROWS * CDIM], g_Olo[MROWS * CDIM];

// ---------------------------------------------------------------------------
// PTX helpers — sm_80-era instruction set (valid under compute_103)
// ---------------------------------------------------------------------------
__device__ __forceinline__ u32 smem_u32(const void* p) {
    u32 a;
    asm("{ .reg .u64 t; cvta.to.shared.u64 t, %1; cvt.u32.u64 %0, t; }"
        : "=r"(a) : "l"(p));
    return a;
}

#define CP_ASYNC16(dst, src) \
    asm volatile("cp.async.cg.shared.global [%0], [%1], 16;" \
        :: "r"(dst), "l"(src) : "memory")
#define CP_COMMIT() asm volatile("cp.async.commit_group;" ::: "memory")
#define CP_WAIT1()  asm volatile("cp.async.wait_group 1;" ::: "memory")

__device__ __forceinline__ void ldmx4(u32& r0, u32& r1, u32& r2, u32& r3, u32 addr) {
    asm volatile("ldmatrix.sync.aligned.m8n8.x4.shared.b16 {%0,%1,%2,%3}, [%4];"
        : "=r"(r0), "=r"(r1), "=r"(r2), "=r"(r3) : "r"(addr));
}

__device__ __forceinline__ void mma16816(float* c, const u32* a, const u32* b) {
    asm volatile(
        "mma.sync.aligned.m16n8k16.row.col.f32.bf16.bf16.f32 "
        "{%0,%1,%2,%3}, {%4,%5,%6,%7}, {%8,%9}, {%0,%1,%2,%3};"
        : "+f"(c[0]), "+f"(c[1]), "+f"(c[2]), "+f"(c[3])
        : "r"(a[0]), "r"(a[1]), "r"(a[2]), "r"(a[3]), "r"(b[0]), "r"(b[1]));
}

__device__ __forceinline__ u32 pack_bf16(float a, float b) {
    __nv_bfloat162 h = __floats2bfloat162_rn(a, b);
    return *(u32*)&h;
}

// ---------------------------------------------------------------------------
// Kernel 0: fp32 -> bf16 hi/lo split. which: 0=x, 1=qkv_w, 2=proj_w
// ---------------------------------------------------------------------------
__global__ __launch_bounds__(256) void cvt_split_kernel(
    const float* __restrict__ src, int n, int which)
{
    int i = (blockIdx.x * 256 + threadIdx.x) * 4;
    if (i >= n) return;
    float4 v = *(const float4*)(src + i);
    __nv_bfloat16 h0 = __float2bfloat16(v.x);
    __nv_bfloat16 h1 = __float2bfloat16(v.y);
    __nv_bfloat16 h2 = __float2bfloat16(v.z);
    __nv_bfloat16 h3 = __float2bfloat16(v.w);
    __nv_bfloat16 l0 = __float2bfloat16(v.x - __bfloat162float(h0));
    __nv_bfloat16 l1 = __float2bfloat16(v.y - __bfloat162float(h1));
    __nv_bfloat16 l2 = __float2bfloat16(v.z - __bfloat162float(h2));
    __nv_bfloat16 l3 = __float2bfloat16(v.w - __bfloat162float(h3));
    __nv_bfloat16* hid = (which == 0) ? g_xhi : (which == 1) ? g_qwhi : g_pwhi;
    __nv_bfloat16* lod = (which == 0) ? g_xlo : (which == 1) ? g_qwlo : g_pwlo;
    __nv_bfloat162 hh0; hh0.x = h0; hh0.y = h1;
    __nv_bfloat162 hh1; hh1.x = h2; hh1.y = h3;
    __nv_bfloat162 ll0; ll0.x = l0; ll0.y = l1;
    __nv_bfloat162 ll1; ll1.x = l2; ll1.y = l3;
    *(__nv_bfloat162*)(hid + i)     = hh0;
    *(__nv_bfloat162*)(hid + i + 2) = hh1;
    *(__nv_bfloat162*)(lod + i)     = ll0;
    *(__nv_bfloat162*)(lod + i + 2) = ll1;
}

// ---------------------------------------------------------------------------
// Kernel 1: mma.sync split-bf16 GEMM.  C[m,o] = sum_k A[m,k] * B[o,k]
// mode 0: A=x, B=qkv_w; epilogue -> bf16 hi/lo Q(*scale)/K [B,H,N,D], Vt [B,H,D,N]
// mode 1: A=attn out, B=proj_w; epilogue adds bias -> fp32 d_out
// ---------------------------------------------------------------------------
#define ARR_BYTES   10240           // 128 * 80
#define STAGE_BYTES 40960
#define SMEM_DYN    81920
#define NSLAB       24

__global__ __launch_bounds__(256, 2) void gemm_tc_kernel(
    int mode, const float* __restrict__ bias, float* __restrict__ out)
{
    extern __shared__ char smem_raw[];
    const u32 smem_base = smem_u32(smem_raw);

    const int tid = threadIdx.x;
    const int wid = tid >> 5;
    const int lane = tid & 31;
    const int warp_m = wid >> 2;
    const int warp_n = wid & 3;
    const int m0 = blockIdx.y * 128;
    const int n0 = blockIdx.x * 128;

    const __nv_bfloat16 *Ahi, *Alo, *Bhi, *Blo;
    if (mode == 0) { Ahi = g_xhi; Alo = g_xlo; Bhi = g_qwhi; Blo = g_qwlo; }
    else           { Ahi = g_Ohi; Alo = g_Olo; Bhi = g_pwhi; Blo = g_pwlo; }

    auto load_slab = [&](int st, int kele) {
        const u32 stb = smem_base + st * STAGE_BYTES;
#pragma unroll
        for (int e = tid; e < 2048; e += 256) {
            const int arr = e >> 9;
            const int i = e & 511;
            const int row = i >> 2, ch = i & 3;
            const __nv_bfloat16* base =
                (arr == 0) ? Ahi : (arr == 1) ? Alo : (arr == 2) ? Bhi : Blo;
            const int grow = ((arr < 2) ? m0 : n0) + row;
            const __nv_bfloat16* src = base + (size_t)grow * KDIM + kele + ch * 8;
            const u32 dst = stb + arr * ARR_BYTES + row * 80 + ch * 16;
            CP_ASYNC16(dst, src);
        }
    };

    float C[4][4][4];
#pragma unroll
    for (int i = 0; i < 4; i++)
#pragma unroll
        for (int j = 0; j < 4; j++)
#pragma unroll
            for (int r = 0; r < 4; r++) C[i][j][r] = 0.0f;

    load_slab(0, 0);  CP_COMMIT();
    load_slab(1, 32); CP_COMMIT();

    const u32 a_row = warp_m * 64 + (lane & 15);
    const u32 a_colh = ((lane >> 4) & 1) * 16;
    const u32 b_row = warp_n * 32 + (lane & 7) + ((lane & 16) >> 1);
    const u32 b_colh = ((lane >> 3) & 1) * 16;

    for (int s = 0; s < NSLAB; s++) {
        CP_WAIT1();
        __syncthreads();
        const u32 stb = smem_base + (s & 1) * STAGE_BYTES;

#pragma unroll
        for (int kk = 0; kk < 2; kk++) {
            const u32 k0b = kk * 32;

            u32 Bh[4][2], Bl[4][2];
#pragma unroll
            for (int np = 0; np < 2; np++) {
                const u32 badr = stb + 2 * ARR_BYTES +
                                 (b_row + np * 16) * 80 + k0b + b_colh;
                u32 r0, r1, r2, r3;
                ldmx4(r0, r1, r2, r3, badr);
                Bh[np * 2][0] = r0; Bh[np * 2][1] = r1;
                Bh[np * 2 + 1][0] = r2; Bh[np * 2 + 1][1] = r3;
                ldmx4(r0, r1, r2, r3, badr + ARR_BYTES);
                Bl[np * 2][0] = r0; Bl[np * 2][1] = r1;
                Bl[np * 2 + 1][0] = r2; Bl[np * 2 + 1][1] = r3;
            }

            u32 A[4][4];
#pragma unroll
            for (int ms = 0; ms < 4; ms++) {
                const u32 aadr = stb + (a_row + ms * 16) * 80 + k0b + a_colh;
                ldmx4(A[ms][0], A[ms][1], A[ms][2], A[ms][3], aadr);
            }
#pragma unroll
            for (int ms = 0; ms < 4; ms++)
#pragma unroll
                for (int ns = 0; ns < 4; ns++) {
                    mma16816(C[ms][ns], A[ms], Bh[ns]);
                    mma16816(C[ms][ns], A[ms], Bl[ns]);
                }

#pragma unroll
            for (int ms = 0; ms < 4; ms++) {
                const u32 aadr = stb + ARR_BYTES + (a_row + ms * 16) * 80 + k0b + a_colh;
                ldmx4(A[ms][0], A[ms][1], A[ms][2], A[ms][3], aadr);
            }
#pragma unroll
            for (int ms = 0; ms < 4; ms++)
#pragma unroll
                for (int ns = 0; ns < 4; ns++)
                    mma16816(C[ms][ns], A[ms], Bh[ns]);
        }

        __syncthreads();
        if (s + 2 < NSLAB) load_slab(s & 1, (s + 2) * 32);
        CP_COMMIT();
    }

    const int r_in = lane >> 2;
    const int c_in = (lane & 3) * 2;
#pragma unroll
    for (int ms = 0; ms < 4; ms++) {
#pragma unroll
        for (int ns = 0; ns < 4; ns++) {
            const int col = n0 + warp_n * 32 + ns * 8 + c_in;
#pragma unroll
            for (int half = 0; half < 2; half++) {
                const int row = m0 + warp_m * 64 + ms * 16 + r_in + half * 8;
                float v0 = C[ms][ns][half * 2 + 0];
                float v1 = C[ms][ns][half * 2 + 1];
                if (mode == 0) {
                    const int which = col / 768;
                    const int rem = col - which * 768;
                    const int h = rem >> 6, d = rem & 63;
                    const int b = row >> 10, n = row & 1023;
                    if (which == 0) { v0 *= QK_SCALE; v1 *= QK_SCALE; }
                    __nv_bfloat16 h0 = __float2bfloat16(v0);
                    __nv_bfloat16 h1 = __float2bfloat16(v1);
                    __nv_bfloat16 l0 = __float2bfloat16(v0 - __bfloat162float(h0));
                    __nv_bfloat16 l1 = __float2bfloat16(v1 - __bfloat162float(h1));
                    if (which < 2) {
                        const size_t idx = ((size_t)(b * NHEAD + h) * NSEQ + n) * DHEAD + d;
                        __nv_bfloat16* dh = (which == 0) ? g_Qhi : g_Khi;
                        __nv_bfloat16* dl = (which == 0) ? g_Qlo : g_Klo;
                        __nv_bfloat162 hh; hh.x = h0; hh.y = h1;
                        __nv_bfloat162 ll; ll.x = l0; ll.y = l1;
                        *(__nv_bfloat162*)(dh + idx) = hh;
                        *(__nv_bfloat162*)(dl + idx) = ll;
                    } else {
                        const size_t idx = ((size_t)(b * NHEAD + h) * DHEAD + d) * NSEQ + n;
                        g_Vthi[idx] = h0; g_Vthi[idx + NSEQ] = h1;
                        g_Vtlo[idx] = l0; g_Vtlo[idx + NSEQ] = l1;
                    }
                } else {
                    const float2 bb = *(const float2*)(bias + col);
                    float2 w = make_float2(v0 + bb.x, v1 + bb.y);
                    *(float2*)(out + (size_t)row * 768 + col) = w;
                }
            }
        }
    }
}

// ---------------------------------------------------------------------------
// Kernel 2: flash attention on tensor cores (split bf16, fp32 softmax).
// 4 warps/CTA, Q-tile 64 (16 rows/warp), K-tile 64, double-buffered cp.async.
// smem: Qhi/Qlo (64x64, 144B stride) + 2 stages x {Khi,Klo,Vthi,Vtlo}.
// ---------------------------------------------------------------------------
#define FA_ARR    9216               // 64 rows * 144B
#define FA_STAGE  36864              // 4 arrays
#define FA_SMEM   (2 * FA_ARR + 2 * FA_STAGE)   // 92160

__global__ __launch_bounds__(128) void flash_attn_tc_kernel()
{
    extern __shared__ char smem_raw[];
    const u32 S0 = smem_u32(smem_raw);

    const int tid = threadIdx.x;
    const int w = tid >> 5;
    const int lane = tid & 31;
    const int qt = blockIdx.x;
    const int h  = blockIdx.y;
    const int b  = blockIdx.z;
    const size_t bh = (size_t)(b * NHEAD + h);

    const __nv_bfloat16* Qhg = g_Qhi + (bh * NSEQ + qt * 64) * DHEAD;
    const __nv_bfloat16* Qlg = g_Qlo + (bh * NSEQ + qt * 64) * DHEAD;
    const __nv_bfloat16* Khg = g_Khi + bh * NSEQ * DHEAD;
    const __nv_bfloat16* Klg = g_Klo + bh * NSEQ * DHEAD;
    const __nv_bfloat16* Vhg = g_Vthi + bh * DHEAD * NSEQ;
    const __nv_bfloat16* Vlg = g_Vtlo + bh * DHEAD * NSEQ;

    // Q tiles (hi,lo): 2 arrays x 64 rows x 8 chunks = 1024 loads / 128 thr
#pragma unroll
    for (int e = tid; e < 1024; e += 128) {
        const int arr = e >> 9;
        const int i = e & 511;
        const int r = i >> 3, ch = i & 7;
        const __nv_bfloat16* src = (arr ? Qlg : Qhg) + r * DHEAD + ch * 8;
        CP_ASYNC16(S0 + arr * FA_ARR + r * 144 + ch * 16, src);
    }

    auto load_kv = [&](int st, int t) {
        const u32 stb = S0 + 2 * FA_ARR + st * FA_STAGE;
#pragma unroll
        for (int e = tid; e < 2048; e += 128) {
            const int arr = e >> 9;          // 0:Khi 1:Klo 2:Vthi 3:Vtlo
            const int i = e & 511;
            const int r = i >> 3, ch = i & 7;
            const __nv_bfloat16* src;
            if (arr < 2) src = (arr ? Klg : Khg) + (size_t)(t * 64 + r) * DHEAD + ch * 8;
            else         src = ((arr == 2) ? Vhg : Vlg) + (size_t)r * NSEQ + t * 64 + ch * 8;
            CP_ASYNC16(stb + arr * FA_ARR + r * 144 + ch * 16, src);
        }
    };

    load_kv(0, 0); CP_COMMIT();     // group 1: Q + stage0
    load_kv(1, 1); CP_COMMIT();     // group 2: stage1

    float O[8][4];
#pragma unroll
    for (int i = 0; i < 8; i++)
#pragma unroll
        for (int j = 0; j < 4; j++) O[i][j] = 0.0f;
    float m0 = -1e30f, m1 = -1e30f, l0 = 0.0f, l1 = 0.0f;

    const u32 qbase = S0 + w * 16 * 144;
    const u32 a_rowoff = (lane & 15) * 144 + ((lane >> 4) & 1) * 16;
    const u32 b_rowsel = (lane & 7) + ((lane & 16) >> 1);
    const u32 b_colh = ((lane >> 3) & 1) * 16;

    for (int t = 0; t < NSEQ / 64; t++) {
        CP_WAIT1();
        __syncthreads();
        const u32 stb = S0 + 2 * FA_ARR + (t & 1) * FA_STAGE;
        const u32 Kh_s = stb, Kl_s = stb + FA_ARR;
        const u32 Vh_s = stb + 2 * FA_ARR, Vl_s = stb + 3 * FA_ARR;

        // ---- S = Q K^T (16x64 per warp), split 3-term ----
        float Sc[8][4];
#pragma unroll
        for (int j = 0; j < 8; j++)
#pragma unroll
            for (int r = 0; r < 4; r++) Sc[j][r] = 0.0f;

#pragma unroll
        for (int kk = 0; kk < 4; kk++) {
            const u32 k0b = kk * 32;
            u32 Ah[4], Al[4];
            ldmx4(Ah[0], Ah[1], Ah[2], Ah[3], qbase + a_rowoff + k0b);
            ldmx4(Al[0], Al[1], Al[2], Al[3], qbase + FA_ARR + a_rowoff + k0b);
#pragma unroll
            for (int kb = 0; kb < 4; kb++) {
                const u32 roff = (kb * 16 + b_rowsel) * 144 + k0b + b_colh;
                u32 h0, h1, h2, h3, q0, q1, q2, q3;
                ldmx4(h0, h1, h2, h3, Kh_s + roff);
                ldmx4(q0, q1, q2, q3, Kl_s + roff);
                u32 bh0[2] = {h0, h1}, bh1[2] = {h2, h3};
                u32 bl0[2] = {q0, q1}, bl1[2] = {q2, q3};
                mma16816(Sc[kb * 2],     Ah, bh0);
                mma16816(Sc[kb * 2],     Ah, bl0);
                mma16816(Sc[kb * 2],     Al, bh0);
                mma16816(Sc[kb * 2 + 1], Ah, bh1);
                mma16816(Sc[kb * 2 + 1], Ah, bl1);
                mma16816(Sc[kb * 2 + 1], Al, bh1);
            }
        }

        // ---- online softmax on fragments (rows r0 = lane>>2, r1 = r0+8) ----
        float mx0 = -1e30f, mx1 = -1e30f;
#pragma unroll
        for (int j = 0; j < 8; j++) {
            mx0 = fmaxf(mx0, fmaxf(Sc[j][0], Sc[j][1]));
            mx1 = fmaxf(mx1, fmaxf(Sc[j][2], Sc[j][3]));
        }
        mx0 = fmaxf(mx0, __shfl_xor_sync(0xffffffffu, mx0, 1));
        mx0 = fmaxf(mx0, __shfl_xor_sync(0xffffffffu, mx0, 2));
        mx1 = fmaxf(mx1, __shfl_xor_sync(0xffffffffu, mx1, 1));
        mx1 = fmaxf(mx1, __shfl_xor_sync(0xffffffffu, mx1, 2));

        const float mn0 = fmaxf(m0, mx0), mn1 = fmaxf(m1, mx1);
        const float cr0 = __expf(m0 - mn0), cr1 = __expf(m1 - mn1);
        m0 = mn0; m1 = mn1;

        float rs0 = 0.0f, rs1 = 0.0f;
#pragma unroll
        for (int j = 0; j < 8; j++) {
            Sc[j][0] = __expf(Sc[j][0] - mn0); rs0 += Sc[j][0];
            Sc[j][1] = __expf(Sc[j][1] - mn0); rs0 += Sc[j][1];
            Sc[j][2] = __expf(Sc[j][2] - mn1); rs1 += Sc[j][2];
            Sc[j][3] = __expf(Sc[j][3] - mn1); rs1 += Sc[j][3];
        }
        rs0 += __shfl_xor_sync(0xffffffffu, rs0, 1);
        rs0 += __shfl_xor_sync(0xffffffffu, rs0, 2);
        rs1 += __shfl_xor_sync(0xffffffffu, rs1, 1);
        rs1 += __shfl_xor_sync(0xffffffffu, rs1, 2);
        l0 = l0 * cr0 + rs0;
        l1 = l1 * cr1 + rs1;

#pragma unroll
        for (int d = 0; d < 8; d++) {
            O[d][0] *= cr0; O[d][1] *= cr0;
            O[d][2] *= cr1; O[d][3] *= cr1;
        }

        // ---- P -> bf16 hi/lo fragments (in registers) ----
        u32 Ph01[8], Ph23[8], Pl01[8], Pl23[8];
#pragma unroll
        for (int j = 0; j < 8; j++) {
            __nv_bfloat162 h01 = __floats2bfloat162_rn(Sc[j][0], Sc[j][1]);
            __nv_bfloat162 h23 = __floats2bfloat162_rn(Sc[j][2], Sc[j][3]);
            Ph01[j] = *(u32*)&h01;
            Ph23[j] = *(u32*)&h23;
            Pl01[j] = pack_bf16(Sc[j][0] - __bfloat162float(h01.x),
                                Sc[j][1] - __bfloat162float(h01.y));
            Pl23[j] = pack_bf16(Sc[j][2] - __bfloat162float(h23.x),
                                Sc[j][3] - __bfloat162float(h23.y));
        }

        // ---- O += P V (16x64 per warp), split 3-term ----
#pragma unroll
        for (int kk2 = 0; kk2 < 4; kk2++) {
            u32 PA[4] = {Ph01[2 * kk2], Ph23[2 * kk2], Ph01[2 * kk2 + 1], Ph23[2 * kk2 + 1]};
            u32 PL[4] = {Pl01[2 * kk2], Pl23[2 * kk2], Pl01[2 * kk2 + 1], Pl23[2 * kk2 + 1]};
            const u32 k0b = kk2 * 32;
#pragma unroll
            for (int ds = 0; ds < 4; ds++) {
                const u32 roff = (ds * 16 + b_rowsel) * 144 + k0b + b_colh;
                u32 h0, h1, h2, h3, q0, q1, q2, q3;
                ldmx4(h0, h1, h2, h3, Vh_s + roff);
                ldmx4(q0, q1, q2, q3, Vl_s + roff);
                u32 vh0[2] = {h0, h1}, vh1[2] = {h2, h3};
                u32 vl0[2] = {q0, q1}, vl1[2] = {q2, q3};
                mma16816(O[ds * 2],     PA, vh0);
                mma16816(O[ds * 2],     PA, vl0);
                mma16816(O[ds * 2],     PL, vh0);
                mma16816(O[ds * 2 + 1], PA, vh1);
                mma16816(O[ds * 2 + 1], PA, vl1);
                mma16816(O[ds * 2 + 1], PL, vh1);
            }
        }

        __syncthreads();
        if (t + 2 < NSEQ / 64) load_kv(t & 1, t + 2);
        CP_COMMIT();
    }

    // ---- epilogue: normalize, split hi/lo, write [B,N,C] ----
    const float inv0 = 1.0f / l0, inv1 = 1.0f / l1;
    const int r0 = lane >> 2;
    const int nrow0 = qt * 64 + w * 16 + r0;
    const int colb = h * 64 + (lane & 3) * 2;
#pragma unroll
    for (int ds = 0; ds < 8; ds++) {
        const int col = colb + ds * 8;
        float v0 = O[ds][0] * inv0, v1 = O[ds][1] * inv0;
        float v2 = O[ds][2] * inv1, v3 = O[ds][3] * inv1;
        __nv_bfloat16 h0 = __float2bfloat16(v0), h1 = __float2bfloat16(v1);
        __nv_bfloat16 h2 = __float2bfloat16(v2), h3 = __float2bfloat16(v3);
        __nv_bfloat162 hh0; hh0.x = h0; hh0.y = h1;
        __nv_bfloat162 hh1; hh1.x = h2; hh1.y = h3;
        __nv_bfloat162 ll0; ll0.x = __float2bfloat16(v0 - __bfloat162float(h0));
        ll0.y = __float2bfloat16(v1 - __bfloat162float(h1));
        __nv_bfloat162 ll1; ll1.x = __float2bfloat16(v2 - __bfloat162float(h2));
        ll1.y = __float2bfloat16(v3 - __bfloat162float(h3));
        const size_t i0 = (size_t)(b * NSEQ + nrow0) * CDIM + col;
        const size_t i1 = (size_t)(b * NSEQ + nrow0 + 8) * CDIM + col;
        *(__nv_bfloat162*)(g_Ohi + i0) = hh0;
        *(__nv_bfloat162*)(g_Olo + i0) = ll0;
        *(__nv_bfloat162*)(g_Ohi + i1) = hh1;
        *(__nv_bfloat162*)(g_Olo + i1) = ll1;
    }
}

// ---------------------------------------------------------------------------
extern "C" void kernel_launch(void* const* d_in, const int* in_sizes, int n_in,
                              void* d_out, int out_size)
{
    const float* x      = (const float*)d_in[0];
    const float* qkv_w  = (const float*)d_in[1];
    const float* proj_w = (const float*)d_in[2];
    const float* proj_b = (const float*)d_in[3];
    float* out = (float*)d_out;

    cudaFuncSetAttribute(gemm_tc_kernel,
                         cudaFuncAttributeMaxDynamicSharedMemorySize, SMEM_DYN);
    cudaFuncSetAttribute(flash_attn_tc_kernel,
                         cudaFuncAttributeMaxDynamicSharedMemorySize, FA_SMEM);

    cvt_split_kernel<<<(MROWS * CDIM) / 1024, 256>>>(x, MROWS * CDIM, 0);
    cvt_split_kernel<<<(3 * CDIM * CDIM) / 1024, 256>>>(qkv_w, 3 * CDIM * CDIM, 1);
    cvt_split_kernel<<<(CDIM * CDIM) / 1024, 256>>>(proj_w, CDIM * CDIM, 2);

    // QKV projection -> bf16 hi/lo Q/K (scaled Q) and transposed V
    gemm_tc_kernel<<<dim3(2304 / 128, MROWS / 128), 256, SMEM_DYN>>>(0, nullptr, nullptr);

    // Flash attention (tensor cores) -> bf16 hi/lo attention output
    flash_attn_tc_kernel<<<dim3(NSEQ / 64, NHEAD, BATCH), 128, FA_SMEM>>>();

    // Output projection (+bias) -> d_out
    gemm_tc_kernel<<<dim3(768 / 128, MROWS / 128), 256, SMEM_DYN>>>(1, proj_b, out);
}

// round 6
// speedup vs baseline: 5.1892x; 1.5106x over previous
#include <cuda_runtime.h>
#include <cuda_fp16.h>
#include <cstdint>
#include <math.h>

#define BATCH 8
#define NSEQ  1024
#define CDIM  768
#define NHEAD 12
#define DHEAD 64
#define MROWS 8192
#define KDIM  768
#define QK_SCALE 0.125f

typedef unsigned long long u64;
typedef unsigned int u32;

// ---------------------------------------------------------------------------
// scratch globals (allocation-free)
// ---------------------------------------------------------------------------
__device__ __half g_xh[MROWS * CDIM],  g_xl[MROWS * CDIM];
__device__ __half g_qw[3 * CDIM * CDIM];              // weights: single fp16
__device__ __half g_pw[CDIM * CDIM];
__device__ __half g_Qh[BATCH * NHEAD * NSEQ * DHEAD]; // Q: hi/lo fp16 (pre-scaled)
__device__ __half g_Ql[BATCH * NHEAD * NSEQ * DHEAD];
__device__ __half g_Kh[BATCH * NHEAD * NSEQ * DHEAD]; // K: single fp16
__device__ __half g_Vt[BATCH * NHEAD * DHEAD * NSEQ]; // V: single fp16, [B,H,D,N]
__device__ __half g_Oh[MROWS * CDIM], g_Ol[MROWS * CDIM];  // attn out hi/lo

// ---------------------------------------------------------------------------
// PTX helpers — sm_80-era instruction set (valid under compute_103)
// ---------------------------------------------------------------------------
__device__ __forceinline__ u32 smem_u32(const void* p) {
    u32 a;
    asm("{ .reg .u64 t; cvta.to.shared.u64 t, %1; cvt.u32.u64 %0, t; }"
        : "=r"(a) : "l"(p));
    return a;
}

#define CP_ASYNC16(dst, src) \
    asm volatile("cp.async.cg.shared.global [%0], [%1], 16;" \
        :: "r"(dst), "l"(src) : "memory")
#define CP_COMMIT() asm volatile("cp.async.commit_group;" ::: "memory")
#define CP_WAIT1()  asm volatile("cp.async.wait_group 1;" ::: "memory")

__device__ __forceinline__ void ldmx4(u32& r0, u32& r1, u32& r2, u32& r3, u32 addr) {
    asm volatile("ldmatrix.sync.aligned.m8n8.x4.shared.b16 {%0,%1,%2,%3}, [%4];"
        : "=r"(r0), "=r"(r1), "=r"(r2), "=r"(r3) : "r"(addr));
}

__device__ __forceinline__ void mma16816(float* c, const u32* a, const u32* b) {
    asm volatile(
        "mma.sync.aligned.m16n8k16.row.col.f32.f16.f16.f32 "
        "{%0,%1,%2,%3}, {%4,%5,%6,%7}, {%8,%9}, {%0,%1,%2,%3};"
        : "+f"(c[0]), "+f"(c[1]), "+f"(c[2]), "+f"(c[3])
        : "r"(a[0]), "r"(a[1]), "r"(a[2]), "r"(a[3]), "r"(b[0]), "r"(b[1]));
}

__device__ __forceinline__ u32 pack_h2(float a, float b) {
    __half2 h = __floats2half2_rn(a, b);
    return *(u32*)&h;
}

// ---------------------------------------------------------------------------
// Kernel 0a: fp32 -> fp16 hi/lo split (x only)
// ---------------------------------------------------------------------------
__global__ __launch_bounds__(256) void cvt_split_kernel(
    const float* __restrict__ src, int n)
{
    int i = (blockIdx.x * 256 + threadIdx.x) * 4;
    if (i >= n) return;
    float4 v = *(const float4*)(src + i);
    __half h0 = __float2half(v.x), h1 = __float2half(v.y);
    __half h2 = __float2half(v.z), h3 = __float2half(v.w);
    union { __half h[4]; uint2 u; } uh, ul;
    uh.h[0] = h0; uh.h[1] = h1; uh.h[2] = h2; uh.h[3] = h3;
    ul.h[0] = __float2half(v.x - __half2float(h0));
    ul.h[1] = __float2half(v.y - __half2float(h1));
    ul.h[2] = __float2half(v.z - __half2float(h2));
    ul.h[3] = __float2half(v.w - __half2float(h3));
    *(uint2*)(g_xh + i) = uh.u;
    *(uint2*)(g_xl + i) = ul.u;
}

// Kernel 0b: fp32 -> fp16 round (weights). which: 0=qkv_w, 1=proj_w
__global__ __launch_bounds__(256) void cvt_round_kernel(
    const float* __restrict__ src, int n, int which)
{
    int i = (blockIdx.x * 256 + threadIdx.x) * 4;
    if (i >= n) return;
    float4 v = *(const float4*)(src + i);
    union { __half h[4]; uint2 u; } uh;
    uh.h[0] = __float2half(v.x); uh.h[1] = __float2half(v.y);
    uh.h[2] = __float2half(v.z); uh.h[3] = __float2half(v.w);
    __half* dst = which ? g_pw : g_qw;
    *(uint2*)(dst + i) = uh.u;
}

// ---------------------------------------------------------------------------
// Kernel 1: mma.sync split-fp16 GEMM.  C[m,o] = sum_k A[m,k] * B[o,k]
//   C = (Ahi + Alo) * B   (2 MMAs per fragment pair, fp32 accum)
// Block 128x128, 8 warps of 64x32, K-slab 32, 2-stage cp.async pipeline.
// smem/stage: 3 arrays (Ah, Al, B) of 128 rows x 32 fp16, 80B stride.
// mode 0: A=x, B=qkv_w -> Q hi/lo (*scale), K single, Vt single transposed
// mode 1: A=attn out (hi/lo), B=proj_w -> +bias, fp32 d_out
// ---------------------------------------------------------------------------
#define ARR_BYTES   10240           // 128 * 80
#define STAGE_BYTES 30720           // 3 arrays
#define SMEM_DYN    61440
#define NSLAB       24

__global__ __launch_bounds__(256, 2) void gemm_tc_kernel(
    int mode, const float* __restrict__ bias, float* __restrict__ out)
{
    extern __shared__ char smem_raw[];
    const u32 smem_base = smem_u32(smem_raw);

    const int tid = threadIdx.x;
    const int wid = tid >> 5;
    const int lane = tid & 31;
    const int warp_m = wid >> 2;
    const int warp_n = wid & 3;
    const int m0 = blockIdx.y * 128;
    const int n0 = blockIdx.x * 128;

    const __half *Ahp, *Alp, *Bp;
    if (mode == 0) { Ahp = g_xh; Alp = g_xl; Bp = g_qw; }
    else           { Ahp = g_Oh; Alp = g_Ol; Bp = g_pw; }

    auto load_slab = [&](int st, int kele) {
        const u32 stb = smem_base + st * STAGE_BYTES;
#pragma unroll
        for (int e = tid; e < 1536; e += 256) {
            const int arr = e >> 9;          // 0:Ah 1:Al 2:B
            const int i = e & 511;
            const int row = i >> 2, ch = i & 3;
            const __half* base = (arr == 0) ? Ahp : (arr == 1) ? Alp : Bp;
            const int grow = ((arr < 2) ? m0 : n0) + row;
            const __half* src = base + (size_t)grow * KDIM + kele + ch * 8;
            const u32 dst = stb + arr * ARR_BYTES + row * 80 + ch * 16;
            CP_ASYNC16(dst, src);
        }
    };

    float C[4][4][4];
#pragma unroll
    for (int i = 0; i < 4; i++)
#pragma unroll
        for (int j = 0; j < 4; j++)
#pragma unroll
            for (int r = 0; r < 4; r++) C[i][j][r] = 0.0f;

    load_slab(0, 0);  CP_COMMIT();
    load_slab(1, 32); CP_COMMIT();

    const u32 a_row = warp_m * 64 + (lane & 15);
    const u32 a_colh = ((lane >> 4) & 1) * 16;
    const u32 b_row = warp_n * 32 + (lane & 7) + ((lane & 16) >> 1);
    const u32 b_colh = ((lane >> 3) & 1) * 16;

    for (int s = 0; s < NSLAB; s++) {
        CP_WAIT1();
        __syncthreads();
        const u32 stb = smem_base + (s & 1) * STAGE_BYTES;

#pragma unroll
        for (int kk = 0; kk < 2; kk++) {
            const u32 k0b = kk * 32;

            u32 Bv[4][2];
#pragma unroll
            for (int np = 0; np < 2; np++) {
                const u32 badr = stb + 2 * ARR_BYTES +
                                 (b_row + np * 16) * 80 + k0b + b_colh;
                u32 r0, r1, r2, r3;
                ldmx4(r0, r1, r2, r3, badr);
                Bv[np * 2][0] = r0; Bv[np * 2][1] = r1;
                Bv[np * 2 + 1][0] = r2; Bv[np * 2 + 1][1] = r3;
            }

            u32 Ah[4][4], Al[4][4];
#pragma unroll
            for (int ms = 0; ms < 4; ms++) {
                const u32 aoff = (a_row + ms * 16) * 80 + k0b + a_colh;
                ldmx4(Ah[ms][0], Ah[ms][1], Ah[ms][2], Ah[ms][3], stb + aoff);
                ldmx4(Al[ms][0], Al[ms][1], Al[ms][2], Al[ms][3],
                      stb + ARR_BYTES + aoff);
            }
#pragma unroll
            for (int ms = 0; ms < 4; ms++)
#pragma unroll
                for (int ns = 0; ns < 4; ns++) {
                    mma16816(C[ms][ns], Ah[ms], Bv[ns]);
                    mma16816(C[ms][ns], Al[ms], Bv[ns]);
                }
        }

        __syncthreads();
        if (s + 2 < NSLAB) load_slab(s & 1, (s + 2) * 32);
        CP_COMMIT();
    }

    const int r_in = lane >> 2;
    const int c_in = (lane & 3) * 2;
#pragma unroll
    for (int ms = 0; ms < 4; ms++) {
#pragma unroll
        for (int ns = 0; ns < 4; ns++) {
            const int col = n0 + warp_n * 32 + ns * 8 + c_in;
#pragma unroll
            for (int half_ = 0; half_ < 2; half_++) {
                const int row = m0 + warp_m * 64 + ms * 16 + r_in + half_ * 8;
                float v0 = C[ms][ns][half_ * 2 + 0];
                float v1 = C[ms][ns][half_ * 2 + 1];
                if (mode == 0) {
                    const int which = col / 768;
                    const int rem = col - which * 768;
                    const int h = rem >> 6, d = rem & 63;
                    const int b = row >> 10, n = row & 1023;
                    if (which == 0) {
                        v0 *= QK_SCALE; v1 *= QK_SCALE;
                        __half h0 = __float2half(v0), h1 = __float2half(v1);
                        union { __half h[2]; u32 u; } hh, ll;
                        hh.h[0] = h0; hh.h[1] = h1;
                        ll.h[0] = __float2half(v0 - __half2float(h0));
                        ll.h[1] = __float2half(v1 - __half2float(h1));
                        const size_t idx = ((size_t)(b * NHEAD + h) * NSEQ + n) * DHEAD + d;
                        *(u32*)(g_Qh + idx) = hh.u;
                        *(u32*)(g_Ql + idx) = ll.u;
                    } else if (which == 1) {
                        union { __half h[2]; u32 u; } hh;
                        hh.h[0] = __float2half(v0); hh.h[1] = __float2half(v1);
                        const size_t idx = ((size_t)(b * NHEAD + h) * NSEQ + n) * DHEAD + d;
                        *(u32*)(g_Kh + idx) = hh.u;
                    } else {
                        const size_t idx = ((size_t)(b * NHEAD + h) * DHEAD + d) * NSEQ + n;
                        g_Vt[idx] = __float2half(v0);
                        g_Vt[idx + NSEQ] = __float2half(v1);
                    }
                } else {
                    const float2 bb = *(const float2*)(bias + col);
                    float2 w = make_float2(v0 + bb.x, v1 + bb.y);
                    *(float2*)(out + (size_t)row * 768 + col) = w;
                }
            }
        }
    }
}

// ---------------------------------------------------------------------------
// Kernel 2: flash attention on tensor cores (fp16, fp32 softmax).
// S = (Qh + Ql) K^T (2 MMAs), O += P V (1 MMA, P & V single fp16).
// 4 warps/CTA, Q-tile 64 (16 rows/warp), K-tile 64, double-buffered cp.async.
// smem: Qh, Ql + 2 stages x {K, Vt}; 144B row stride.
// ---------------------------------------------------------------------------
#define FA_ARR    9216               // 64 rows * 144B
#define FA_STAGE  18432              // 2 arrays (K, Vt)
#define FA_SMEM   (2 * FA_ARR + 2 * FA_STAGE)   // 55296

__global__ __launch_bounds__(128) void flash_attn_tc_kernel()
{
    extern __shared__ char smem_raw[];
    const u32 S0 = smem_u32(smem_raw);

    const int tid = threadIdx.x;
    const int w = tid >> 5;
    const int lane = tid & 31;
    const int qt = blockIdx.x;
    const int h  = blockIdx.y;
    const int b  = blockIdx.z;
    const size_t bh = (size_t)(b * NHEAD + h);

    const __half* Qhg = g_Qh + (bh * NSEQ + qt * 64) * DHEAD;
    const __half* Qlg = g_Ql + (bh * NSEQ + qt * 64) * DHEAD;
    const __half* Kg  = g_Kh + bh * NSEQ * DHEAD;
    const __half* Vg  = g_Vt + bh * DHEAD * NSEQ;

    // Q tiles (hi,lo): 2 arrays x 64 rows x 8 chunks
#pragma unroll
    for (int e = tid; e < 1024; e += 128) {
        const int arr = e >> 9;
        const int i = e & 511;
        const int r = i >> 3, ch = i & 7;
        const __half* src = (arr ? Qlg : Qhg) + r * DHEAD + ch * 8;
        CP_ASYNC16(S0 + arr * FA_ARR + r * 144 + ch * 16, src);
    }

    auto load_kv = [&](int st, int t) {
        const u32 stb = S0 + 2 * FA_ARR + st * FA_STAGE;
#pragma unroll
        for (int e = tid; e < 1024; e += 128) {
            const int arr = e >> 9;          // 0:K 1:Vt
            const int i = e & 511;
            const int r = i >> 3, ch = i & 7;
            const __half* src;
            if (arr == 0) src = Kg + (size_t)(t * 64 + r) * DHEAD + ch * 8;
            else          src = Vg + (size_t)r * NSEQ + t * 64 + ch * 8;
            CP_ASYNC16(stb + arr * FA_ARR + r * 144 + ch * 16, src);
        }
    };

    load_kv(0, 0); CP_COMMIT();
    load_kv(1, 1); CP_COMMIT();

    float O[8][4];
#pragma unroll
    for (int i = 0; i < 8; i++)
#pragma unroll
        for (int j = 0; j < 4; j++) O[i][j] = 0.0f;
    float m0 = -1e30f, m1 = -1e30f, l0 = 0.0f, l1 = 0.0f;

    const u32 qbase = S0 + w * 16 * 144;
    const u32 a_rowoff = (lane & 15) * 144 + ((lane >> 4) & 1) * 16;
    const u32 b_rowsel = (lane & 7) + ((lane & 16) >> 1);
    const u32 b_colh = ((lane >> 3) & 1) * 16;

    for (int t = 0; t < NSEQ / 64; t++) {
        CP_WAIT1();
        __syncthreads();
        const u32 stb = S0 + 2 * FA_ARR + (t & 1) * FA_STAGE;
        const u32 K_s = stb, V_s = stb + FA_ARR;

        // ---- S = Q K^T (16x64 per warp), 2-term ----
        float Sc[8][4];
#pragma unroll
        for (int j = 0; j < 8; j++)
#pragma unroll
            for (int r = 0; r < 4; r++) Sc[j][r] = 0.0f;

#pragma unroll
        for (int kk = 0; kk < 4; kk++) {
            const u32 k0b = kk * 32;
            u32 Ah[4], Al[4];
            ldmx4(Ah[0], Ah[1], Ah[2], Ah[3], qbase + a_rowoff + k0b);
            ldmx4(Al[0], Al[1], Al[2], Al[3], qbase + FA_ARR + a_rowoff + k0b);
#pragma unroll
            for (int kb = 0; kb < 4; kb++) {
                const u32 roff = (kb * 16 + b_rowsel) * 144 + k0b + b_colh;
                u32 r0, r1, r2, r3;
                ldmx4(r0, r1, r2, r3, K_s + roff);
                u32 b0[2] = {r0, r1}, b1[2] = {r2, r3};
                mma16816(Sc[kb * 2],     Ah, b0);
                mma16816(Sc[kb * 2],     Al, b0);
                mma16816(Sc[kb * 2 + 1], Ah, b1);
                mma16816(Sc[kb * 2 + 1], Al, b1);
            }
        }

        // ---- online softmax (rows r0 = lane>>2, r1 = r0+8) ----
        float mx0 = -1e30f, mx1 = -1e30f;
#pragma unroll
        for (int j = 0; j < 8; j++) {
            mx0 = fmaxf(mx0, fmaxf(Sc[j][0], Sc[j][1]));
            mx1 = fmaxf(mx1, fmaxf(Sc[j][2], Sc[j][3]));
        }
        mx0 = fmaxf(mx0, __shfl_xor_sync(0xffffffffu, mx0, 1));
        mx0 = fmaxf(mx0, __shfl_xor_sync(0xffffffffu, mx0, 2));
        mx1 = fmaxf(mx1, __shfl_xor_sync(0xffffffffu, mx1, 1));
        mx1 = fmaxf(mx1, __shfl_xor_sync(0xffffffffu, mx1, 2));

        const float mn0 = fmaxf(m0, mx0), mn1 = fmaxf(m1, mx1);
        const float cr0 = __expf(m0 - mn0), cr1 = __expf(m1 - mn1);
        m0 = mn0; m1 = mn1;

        float rs0 = 0.0f, rs1 = 0.0f;
#pragma unroll
        for (int j = 0; j < 8; j++) {
            Sc[j][0] = __expf(Sc[j][0] - mn0); rs0 += Sc[j][0];
            Sc[j][1] = __expf(Sc[j][1] - mn0); rs0 += Sc[j][1];
            Sc[j][2] = __expf(Sc[j][2] - mn1); rs1 += Sc[j][2];
            Sc[j][3] = __expf(Sc[j][3] - mn1); rs1 += Sc[j][3];
        }
        rs0 += __shfl_xor_sync(0xffffffffu, rs0, 1);
        rs0 += __shfl_xor_sync(0xffffffffu, rs0, 2);
        rs1 += __shfl_xor_sync(0xffffffffu, rs1, 1);
        rs1 += __shfl_xor_sync(0xffffffffu, rs1, 2);
        l0 = l0 * cr0 + rs0;
        l1 = l1 * cr1 + rs1;

#pragma unroll
        for (int d = 0; d < 8; d++) {
            O[d][0] *= cr0; O[d][1] *= cr0;
            O[d][2] *= cr1; O[d][3] *= cr1;
        }

        // ---- P -> single fp16 fragments ----
        u32 Pp01[8], Pp23[8];
#pragma unroll
        for (int j = 0; j < 8; j++) {
            Pp01[j] = pack_h2(Sc[j][0], Sc[j][1]);
            Pp23[j] = pack_h2(Sc[j][2], Sc[j][3]);
        }

        // ---- O += P V (16x64 per warp), 1 MMA per fragment pair ----
#pragma unroll
        for (int kk2 = 0; kk2 < 4; kk2++) {
            u32 PA[4] = {Pp01[2 * kk2], Pp23[2 * kk2],
                         Pp01[2 * kk2 + 1], Pp23[2 * kk2 + 1]};
            const u32 k0b = kk2 * 32;
#pragma unroll
            for (int ds = 0; ds < 4; ds++) {
                const u32 roff = (ds * 16 + b_rowsel) * 144 + k0b + b_colh;
                u32 r0, r1, r2, r3;
                ldmx4(r0, r1, r2, r3, V_s + roff);
                u32 v0[2] = {r0, r1}, v1[2] = {r2, r3};
                mma16816(O[ds * 2],     PA, v0);
                mma16816(O[ds * 2 + 1], PA, v1);
            }
        }

        __syncthreads();
        if (t + 2 < NSEQ / 64) load_kv(t & 1, t + 2);
        CP_COMMIT();
    }

    // ---- epilogue: normalize, split fp16 hi/lo, write [B,N,C] ----
    const float inv0 = 1.0f / l0, inv1 = 1.0f / l1;
    const int r0 = lane >> 2;
    const int nrow0 = qt * 64 + w * 16 + r0;
    const int colb = h * 64 + (lane & 3) * 2;
#pragma unroll
    for (int ds = 0; ds < 8; ds++) {
        const int col = colb + ds * 8;
        float v0 = O[ds][0] * inv0, v1 = O[ds][1] * inv0;
        float v2 = O[ds][2] * inv1, v3 = O[ds][3] * inv1;
        __half h0 = __float2half(v0), h1 = __float2half(v1);
        __half h2 = __float2half(v2), h3 = __float2half(v3);
        union { __half h[2]; u32 u; } hh0, hh1, ll0, ll1;
        hh0.h[0] = h0; hh0.h[1] = h1;
        hh1.h[0] = h2; hh1.h[1] = h3;
        ll0.h[0] = __float2half(v0 - __half2float(h0));
        ll0.h[1] = __float2half(v1 - __half2float(h1));
        ll1.h[0] = __float2half(v2 - __half2float(h2));
        ll1.h[1] = __float2half(v3 - __half2float(h3));
        const size_t i0 = (size_t)(b * NSEQ + nrow0) * CDIM + col;
        const size_t i1 = (size_t)(b * NSEQ + nrow0 + 8) * CDIM + col;
        *(u32*)(g_Oh + i0) = hh0.u;
        *(u32*)(g_Ol + i0) = ll0.u;
        *(u32*)(g_Oh + i1) = hh1.u;
        *(u32*)(g_Ol + i1) = ll1.u;
    }
}

// ---------------------------------------------------------------------------
extern "C" void kernel_launch(void* const* d_in, const int* in_sizes, int n_in,
                              void* d_out, int out_size)
{
    const float* x      = (const float*)d_in[0];
    const float* qkv_w  = (const float*)d_in[1];
    const float* proj_w = (const float*)d_in[2];
    const float* proj_b = (const float*)d_in[3];
    float* out = (float*)d_out;

    cudaFuncSetAttribute(gemm_tc_kernel,
                         cudaFuncAttributeMaxDynamicSharedMemorySize, SMEM_DYN);
    cudaFuncSetAttribute(flash_attn_tc_kernel,
                         cudaFuncAttributeMaxDynamicSharedMemorySize, FA_SMEM);

    cvt_split_kernel<<<(MROWS * CDIM) / 1024, 256>>>(x, MROWS * CDIM);
    cvt_round_kernel<<<(3 * CDIM * CDIM) / 1024, 256>>>(qkv_w, 3 * CDIM * CDIM, 0);
    cvt_round_kernel<<<(CDIM * CDIM) / 1024, 256>>>(proj_w, CDIM * CDIM, 1);

    // QKV projection -> Q hi/lo (scaled), K single, Vt single
    gemm_tc_kernel<<<dim3(2304 / 128, MROWS / 128), 256, SMEM_DYN>>>(0, nullptr, nullptr);

    // Flash attention (tensor cores) -> fp16 hi/lo attention output
    flash_attn_tc_kernel<<<dim3(NSEQ / 64, NHEAD, BATCH), 128, FA_SMEM>>>();

    // Output projection (+bias) -> d_out
    gemm_tc_kernel<<<dim3(768 / 128, MROWS / 128), 256, SMEM_DYN>>>(1, proj_b, out);
}

// round 7
// speedup vs baseline: 7.7614x; 1.4957x over previous
#include <cuda_runtime.h>
#include <cuda_fp16.h>
#include <cstdint>
#include <math.h>

#define BATCH 8
#define NSEQ  1024
#define CDIM  768
#define NHEAD 12
#define DHEAD 64
#define MROWS 8192
#define KDIM  768
#define QK_SCALE 0.125f

typedef unsigned long long u64;
typedef unsigned int u32;

// ---------------------------------------------------------------------------
// scratch globals (allocation-free) — all single fp16
// ---------------------------------------------------------------------------
__device__ __half g_x[MROWS * CDIM];
__device__ __half g_qw[3 * CDIM * CDIM];
__device__ __half g_pw[CDIM * CDIM];
__device__ __half g_Qh[BATCH * NHEAD * NSEQ * DHEAD];  // pre-scaled
__device__ __half g_Kh[BATCH * NHEAD * NSEQ * DHEAD];
__device__ __half g_Vt[BATCH * NHEAD * DHEAD * NSEQ];  // [B,H,D,N]
__device__ __half g_O[MROWS * CDIM];                   // attn out [B,N,C]

// ---------------------------------------------------------------------------
// PTX helpers — sm_80-era instruction set (valid under compute_103)
// ---------------------------------------------------------------------------
__device__ __forceinline__ u32 smem_u32(const void* p) {
    u32 a;
    asm("{ .reg .u64 t; cvta.to.shared.u64 t, %1; cvt.u32.u64 %0, t; }"
        : "=r"(a) : "l"(p));
    return a;
}

#define CP_ASYNC16(dst, src) \
    asm volatile("cp.async.cg.shared.global [%0], [%1], 16;" \
        :: "r"(dst), "l"(src) : "memory")
#define CP_COMMIT() asm volatile("cp.async.commit_group;" ::: "memory")
#define CP_WAIT1()  asm volatile("cp.async.wait_group 1;" ::: "memory")

__device__ __forceinline__ void ldmx4(u32& r0, u32& r1, u32& r2, u32& r3, u32 addr) {
    asm volatile("ldmatrix.sync.aligned.m8n8.x4.shared.b16 {%0,%1,%2,%3}, [%4];"
        : "=r"(r0), "=r"(r1), "=r"(r2), "=r"(r3) : "r"(addr));
}

__device__ __forceinline__ void mma16816(float* c, const u32* a, const u32* b) {
    asm volatile(
        "mma.sync.aligned.m16n8k16.row.col.f32.f16.f16.f32 "
        "{%0,%1,%2,%3}, {%4,%5,%6,%7}, {%8,%9}, {%0,%1,%2,%3};"
        : "+f"(c[0]), "+f"(c[1]), "+f"(c[2]), "+f"(c[3])
        : "r"(a[0]), "r"(a[1]), "r"(a[2]), "r"(a[3]), "r"(b[0]), "r"(b[1]));
}

__device__ __forceinline__ u32 pack_h2(float a, float b) {
    __half2 h = __floats2half2_rn(a, b);
    return *(u32*)&h;
}

// ---------------------------------------------------------------------------
// Kernel 0: fp32 -> fp16 round. which: 0=x, 1=qkv_w, 2=proj_w
// ---------------------------------------------------------------------------
__global__ __launch_bounds__(256) void cvt_round_kernel(
    const float* __restrict__ src, int n, int which)
{
    int i = (blockIdx.x * 256 + threadIdx.x) * 4;
    if (i >= n) return;
    float4 v = *(const float4*)(src + i);
    union { __half h[4]; uint2 u; } uh;
    uh.h[0] = __float2half(v.x); uh.h[1] = __float2half(v.y);
    uh.h[2] = __float2half(v.z); uh.h[3] = __float2half(v.w);
    __half* dst = (which == 0) ? g_x : (which == 1) ? g_qw : g_pw;
    *(uint2*)(dst + i) = uh.u;
}

// ---------------------------------------------------------------------------
// Kernel 1: mma.sync fp16 GEMM.  C[m,o] = sum_k A[m,k] * B[o,k]  (fp32 accum)
// Block 128x128, 8 warps of 64x32, K-slab 32, 2-stage cp.async pipeline.
// smem/stage: 2 arrays (A, B) of 128 rows x 32 fp16, 80B stride.
// mode 0: A=x, B=qkv_w -> Q(*scale)/K [B,H,N,D], Vt [B,H,D,N]
// mode 1: A=attn out, B=proj_w -> +bias, fp32 d_out
// ---------------------------------------------------------------------------
#define ARR_BYTES   10240           // 128 * 80
#define STAGE_BYTES 20480           // 2 arrays
#define SMEM_DYN    40960
#define NSLAB       24

__global__ __launch_bounds__(256, 2) void gemm_tc_kernel(
    int mode, const float* __restrict__ bias, float* __restrict__ out)
{
    extern __shared__ char smem_raw[];
    const u32 smem_base = smem_u32(smem_raw);

    const int tid = threadIdx.x;
    const int wid = tid >> 5;
    const int lane = tid & 31;
    const int warp_m = wid >> 2;
    const int warp_n = wid & 3;
    const int m0 = blockIdx.y * 128;
    const int n0 = blockIdx.x * 128;

    const __half *Ap, *Bp;
    if (mode == 0) { Ap = g_x; Bp = g_qw; }
    else           { Ap = g_O; Bp = g_pw; }

    auto load_slab = [&](int st, int kele) {
        const u32 stb = smem_base + st * STAGE_BYTES;
#pragma unroll
        for (int e = tid; e < 1024; e += 256) {
            const int arr = e >> 9;          // 0:A 1:B
            const int i = e & 511;
            const int row = i >> 2, ch = i & 3;
            const __half* base = arr ? Bp : Ap;
            const int grow = (arr ? n0 : m0) + row;
            const __half* src = base + (size_t)grow * KDIM + kele + ch * 8;
            const u32 dst = stb + arr * ARR_BYTES + row * 80 + ch * 16;
            CP_ASYNC16(dst, src);
        }
    };

    float C[4][4][4];
#pragma unroll
    for (int i = 0; i < 4; i++)
#pragma unroll
        for (int j = 0; j < 4; j++)
#pragma unroll
            for (int r = 0; r < 4; r++) C[i][j][r] = 0.0f;

    load_slab(0, 0);  CP_COMMIT();
    load_slab(1, 32); CP_COMMIT();

    const u32 a_row = warp_m * 64 + (lane & 15);
    const u32 a_colh = ((lane >> 4) & 1) * 16;
    const u32 b_row = warp_n * 32 + (lane & 7) + ((lane & 16) >> 1);
    const u32 b_colh = ((lane >> 3) & 1) * 16;

    for (int s = 0; s < NSLAB; s++) {
        CP_WAIT1();
        __syncthreads();
        const u32 stb = smem_base + (s & 1) * STAGE_BYTES;

#pragma unroll
        for (int kk = 0; kk < 2; kk++) {
            const u32 k0b = kk * 32;

            u32 Bv[4][2];
#pragma unroll
            for (int np = 0; np < 2; np++) {
                const u32 badr = stb + ARR_BYTES +
                                 (b_row + np * 16) * 80 + k0b + b_colh;
                u32 r0, r1, r2, r3;
                ldmx4(r0, r1, r2, r3, badr);
                Bv[np * 2][0] = r0; Bv[np * 2][1] = r1;
                Bv[np * 2 + 1][0] = r2; Bv[np * 2 + 1][1] = r3;
            }

            u32 A[4][4];
#pragma unroll
            for (int ms = 0; ms < 4; ms++) {
                const u32 aoff = (a_row + ms * 16) * 80 + k0b + a_colh;
                ldmx4(A[ms][0], A[ms][1], A[ms][2], A[ms][3], stb + aoff);
            }
#pragma unroll
            for (int ms = 0; ms < 4; ms++)
#pragma unroll
                for (int ns = 0; ns < 4; ns++)
                    mma16816(C[ms][ns], A[ms], Bv[ns]);
        }

        __syncthreads();
        if (s + 2 < NSLAB) load_slab(s & 1, (s + 2) * 32);
        CP_COMMIT();
    }

    const int r_in = lane >> 2;
    const int c_in = (lane & 3) * 2;
#pragma unroll
    for (int ms = 0; ms < 4; ms++) {
#pragma unroll
        for (int ns = 0; ns < 4; ns++) {
            const int col = n0 + warp_n * 32 + ns * 8 + c_in;
#pragma unroll
            for (int half_ = 0; half_ < 2; half_++) {
                const int row = m0 + warp_m * 64 + ms * 16 + r_in + half_ * 8;
                float v0 = C[ms][ns][half_ * 2 + 0];
                float v1 = C[ms][ns][half_ * 2 + 1];
                if (mode == 0) {
                    const int which = col / 768;
                    const int rem = col - which * 768;
                    const int h = rem >> 6, d = rem & 63;
                    const int b = row >> 10, n = row & 1023;
                    if (which == 0) { v0 *= QK_SCALE; v1 *= QK_SCALE; }
                    if (which < 2) {
                        union { __half h[2]; u32 u; } hh;
                        hh.h[0] = __float2half(v0); hh.h[1] = __float2half(v1);
                        const size_t idx = ((size_t)(b * NHEAD + h) * NSEQ + n) * DHEAD + d;
                        __half* dst = (which == 0) ? g_Qh : g_Kh;
                        *(u32*)(dst + idx) = hh.u;
                    } else {
                        const size_t idx = ((size_t)(b * NHEAD + h) * DHEAD + d) * NSEQ + n;
                        g_Vt[idx] = __float2half(v0);
                        g_Vt[idx + NSEQ] = __float2half(v1);
                    }
                } else {
                    const float2 bb = *(const float2*)(bias + col);
                    float2 w = make_float2(v0 + bb.x, v1 + bb.y);
                    *(float2*)(out + (size_t)row * 768 + col) = w;
                }
            }
        }
    }
}

// ---------------------------------------------------------------------------
// Kernel 2: flash attention on tensor cores (fp16 inputs, fp32 softmax/accum).
// 4 warps/CTA, Q-tile 64 (16 rows/warp), K-tile 64, double-buffered cp.async.
// smem: Q + 2 stages x {K, Vt}; 144B row stride.
// ---------------------------------------------------------------------------
#define FA_ARR    9216               // 64 rows * 144B
#define FA_STAGE  18432              // 2 arrays (K, Vt)
#define FA_SMEM   (FA_ARR + 2 * FA_STAGE)   // 46080

__global__ __launch_bounds__(128) void flash_attn_tc_kernel()
{
    extern __shared__ char smem_raw[];
    const u32 S0 = smem_u32(smem_raw);

    const int tid = threadIdx.x;
    const int w = tid >> 5;
    const int lane = tid & 31;
    const int qt = blockIdx.x;
    const int h  = blockIdx.y;
    const int b  = blockIdx.z;
    const size_t bh = (size_t)(b * NHEAD + h);

    const __half* Qg = g_Qh + (bh * NSEQ + qt * 64) * DHEAD;
    const __half* Kg = g_Kh + bh * NSEQ * DHEAD;
    const __half* Vg = g_Vt + bh * DHEAD * NSEQ;

    // Q tile: 64 rows x 8 chunks of 16B
#pragma unroll
    for (int e = tid; e < 512; e += 128) {
        const int r = e >> 3, ch = e & 7;
        CP_ASYNC16(S0 + r * 144 + ch * 16, Qg + r * DHEAD + ch * 8);
    }

    auto load_kv = [&](int st, int t) {
        const u32 stb = S0 + FA_ARR + st * FA_STAGE;
#pragma unroll
        for (int e = tid; e < 1024; e += 128) {
            const int arr = e >> 9;          // 0:K 1:Vt
            const int i = e & 511;
            const int r = i >> 3, ch = i & 7;
            const __half* src;
            if (arr == 0) src = Kg + (size_t)(t * 64 + r) * DHEAD + ch * 8;
            else          src = Vg + (size_t)r * NSEQ + t * 64 + ch * 8;
            CP_ASYNC16(stb + arr * FA_ARR + r * 144 + ch * 16, src);
        }
    };

    load_kv(0, 0); CP_COMMIT();
    load_kv(1, 1); CP_COMMIT();

    float O[8][4];
#pragma unroll
    for (int i = 0; i < 8; i++)
#pragma unroll
        for (int j = 0; j < 4; j++) O[i][j] = 0.0f;
    float m0 = -1e30f, m1 = -1e30f, l0 = 0.0f, l1 = 0.0f;

    const u32 qbase = S0 + w * 16 * 144;
    const u32 a_rowoff = (lane & 15) * 144 + ((lane >> 4) & 1) * 16;
    const u32 b_rowsel = (lane & 7) + ((lane & 16) >> 1);
    const u32 b_colh = ((lane >> 3) & 1) * 16;

    for (int t = 0; t < NSEQ / 64; t++) {
        CP_WAIT1();
        __syncthreads();
        const u32 stb = S0 + FA_ARR + (t & 1) * FA_STAGE;
        const u32 K_s = stb, V_s = stb + FA_ARR;

        // ---- S = Q K^T (16x64 per warp) ----
        float Sc[8][4];
#pragma unroll
        for (int j = 0; j < 8; j++)
#pragma unroll
            for (int r = 0; r < 4; r++) Sc[j][r] = 0.0f;

#pragma unroll
        for (int kk = 0; kk < 4; kk++) {
            const u32 k0b = kk * 32;
            u32 Aq[4];
            ldmx4(Aq[0], Aq[1], Aq[2], Aq[3], qbase + a_rowoff + k0b);
#pragma unroll
            for (int kb = 0; kb < 4; kb++) {
                const u32 roff = (kb * 16 + b_rowsel) * 144 + k0b + b_colh;
                u32 r0, r1, r2, r3;
                ldmx4(r0, r1, r2, r3, K_s + roff);
                u32 b0[2] = {r0, r1}, b1[2] = {r2, r3};
                mma16816(Sc[kb * 2],     Aq, b0);
                mma16816(Sc[kb * 2 + 1], Aq, b1);
            }
        }

        // ---- online softmax (rows r0 = lane>>2, r1 = r0+8) ----
        float mx0 = -1e30f, mx1 = -1e30f;
#pragma unroll
        for (int j = 0; j < 8; j++) {
            mx0 = fmaxf(mx0, fmaxf(Sc[j][0], Sc[j][1]));
            mx1 = fmaxf(mx1, fmaxf(Sc[j][2], Sc[j][3]));
        }
        mx0 = fmaxf(mx0, __shfl_xor_sync(0xffffffffu, mx0, 1));
        mx0 = fmaxf(mx0, __shfl_xor_sync(0xffffffffu, mx0, 2));
        mx1 = fmaxf(mx1, __shfl_xor_sync(0xffffffffu, mx1, 1));
        mx1 = fmaxf(mx1, __shfl_xor_sync(0xffffffffu, mx1, 2));

        const float mn0 = fmaxf(m0, mx0), mn1 = fmaxf(m1, mx1);
        const float cr0 = __expf(m0 - mn0), cr1 = __expf(m1 - mn1);
        m0 = mn0; m1 = mn1;

        float rs0 = 0.0f, rs1 = 0.0f;
#pragma unroll
        for (int j = 0; j < 8; j++) {
            Sc[j][0] = __expf(Sc[j][0] - mn0); rs0 += Sc[j][0];
            Sc[j][1] = __expf(Sc[j][1] - mn0); rs0 += Sc[j][1];
            Sc[j][2] = __expf(Sc[j][2] - mn1); rs1 += Sc[j][2];
            Sc[j][3] = __expf(Sc[j][3] - mn1); rs1 += Sc[j][3];
        }
        rs0 += __shfl_xor_sync(0xffffffffu, rs0, 1);
        rs0 += __shfl_xor_sync(0xffffffffu, rs0, 2);
        rs1 += __shfl_xor_sync(0xffffffffu, rs1, 1);
        rs1 += __shfl_xor_sync(0xffffffffu, rs1, 2);
        l0 = l0 * cr0 + rs0;
        l1 = l1 * cr1 + rs1;

#pragma unroll
        for (int d = 0; d < 8; d++) {
            O[d][0] *= cr0; O[d][1] *= cr0;
            O[d][2] *= cr1; O[d][3] *= cr1;
        }

        // ---- P -> fp16 fragments ----
        u32 Pp01[8], Pp23[8];
#pragma unroll
        for (int j = 0; j < 8; j++) {
            Pp01[j] = pack_h2(Sc[j][0], Sc[j][1]);
            Pp23[j] = pack_h2(Sc[j][2], Sc[j][3]);
        }

        // ---- O += P V (16x64 per warp) ----
#pragma unroll
        for (int kk2 = 0; kk2 < 4; kk2++) {
            u32 PA[4] = {Pp01[2 * kk2], Pp23[2 * kk2],
                         Pp01[2 * kk2 + 1], Pp23[2 * kk2 + 1]};
            const u32 k0b = kk2 * 32;
#pragma unroll
            for (int ds = 0; ds < 4; ds++) {
                const u32 roff = (ds * 16 + b_rowsel) * 144 + k0b + b_colh;
                u32 r0, r1, r2, r3;
                ldmx4(r0, r1, r2, r3, V_s + roff);
                u32 v0[2] = {r0, r1}, v1[2] = {r2, r3};
                mma16816(O[ds * 2],     PA, v0);
                mma16816(O[ds * 2 + 1], PA, v1);
            }
        }

        __syncthreads();
        if (t + 2 < NSEQ / 64) load_kv(t & 1, t + 2);
        CP_COMMIT();
    }

    // ---- epilogue: normalize, round fp16, write [B,N,C] ----
    const float inv0 = 1.0f / l0, inv1 = 1.0f / l1;
    const int r0 = lane >> 2;
    const int nrow0 = qt * 64 + w * 16 + r0;
    const int colb = h * 64 + (lane & 3) * 2;
#pragma unroll
    for (int ds = 0; ds < 8; ds++) {
        const int col = colb + ds * 8;
        const u32 u0 = pack_h2(O[ds][0] * inv0, O[ds][1] * inv0);
        const u32 u1 = pack_h2(O[ds][2] * inv1, O[ds][3] * inv1);
        const size_t i0 = (size_t)(b * NSEQ + nrow0) * CDIM + col;
        const size_t i1 = (size_t)(b * NSEQ + nrow0 + 8) * CDIM + col;
        *(u32*)(g_O + i0) = u0;
        *(u32*)(g_O + i1) = u1;
    }
}

// ---------------------------------------------------------------------------
extern "C" void kernel_launch(void* const* d_in, const int* in_sizes, int n_in,
                              void* d_out, int out_size)
{
    const float* x      = (const float*)d_in[0];
    const float* qkv_w  = (const float*)d_in[1];
    const float* proj_w = (const float*)d_in[2];
    const float* proj_b = (const float*)d_in[3];
    float* out = (float*)d_out;

    cudaFuncSetAttribute(gemm_tc_kernel,
                         cudaFuncAttributeMaxDynamicSharedMemorySize, SMEM_DYN);
    cudaFuncSetAttribute(flash_attn_tc_kernel,
                         cudaFuncAttributeMaxDynamicSharedMemorySize, FA_SMEM);

    cvt_round_kernel<<<(MROWS * CDIM) / 1024, 256>>>(x, MROWS * CDIM, 0);
    cvt_round_kernel<<<(3 * CDIM * CDIM) / 1024, 256>>>(qkv_w, 3 * CDIM * CDIM, 1);
    cvt_round_kernel<<<(CDIM * CDIM) / 1024, 256>>>(proj_w, CDIM * CDIM, 2);

    // QKV projection -> Q(*scale)/K, Vt
    gemm_tc_kernel<<<dim3(2304 / 128, MROWS / 128), 256, SMEM_DYN>>>(0, nullptr, nullptr);

    // Flash attention (tensor cores)
    flash_attn_tc_kernel<<<dim3(NSEQ / 64, NHEAD, BATCH), 128, FA_SMEM>>>();

    // Output projection (+bias) -> d_out
    gemm_tc_kernel<<<dim3(768 / 128, MROWS / 128), 256, SMEM_DYN>>>(1, proj_b, out);
}

// round 8
// speedup vs baseline: 8.2230x; 1.0595x over previous
#include <cuda_runtime.h>
#include <cuda_fp16.h>
#include <cstdint>
#include <math.h>

#define BATCH 8
#define NSEQ  1024
#define CDIM  768
#define NHEAD 12
#define DHEAD 64
#define MROWS 8192
#define KDIM  768
#define QK_SCALE 0.125f

typedef unsigned long long u64;
typedef unsigned int u32;

// ---------------------------------------------------------------------------
// scratch globals (allocation-free) — all single fp16
// ---------------------------------------------------------------------------
__device__ __half g_x[MROWS * CDIM];
__device__ __half g_qw[3 * CDIM * CDIM];
__device__ __half g_pw[CDIM * CDIM];
__device__ __half g_Qh[BATCH * NHEAD * NSEQ * DHEAD];  // pre-scaled
__device__ __half g_Kh[BATCH * NHEAD * NSEQ * DHEAD];
__device__ __half g_Vt[BATCH * NHEAD * DHEAD * NSEQ];  // [B,H,D,N]
__device__ __half g_O[MROWS * CDIM];                   // attn out [B,N,C]

// ---------------------------------------------------------------------------
// PTX helpers — sm_80-era instruction set (valid under compute_103)
// ---------------------------------------------------------------------------
__device__ __forceinline__ u32 smem_u32(const void* p) {
    u32 a;
    asm("{ .reg .u64 t; cvta.to.shared.u64 t, %1; cvt.u32.u64 %0, t; }"
        : "=r"(a) : "l"(p));
    return a;
}

#define CP_ASYNC16(dst, src) \
    asm volatile("cp.async.cg.shared.global [%0], [%1], 16;" \
        :: "r"(dst), "l"(src) : "memory")
#define CP_COMMIT() asm volatile("cp.async.commit_group;" ::: "memory")
#define CP_WAIT1()  asm volatile("cp.async.wait_group 1;" ::: "memory")

__device__ __forceinline__ void ldmx4(u32& r0, u32& r1, u32& r2, u32& r3, u32 addr) {
    asm volatile("ldmatrix.sync.aligned.m8n8.x4.shared.b16 {%0,%1,%2,%3}, [%4];"
        : "=r"(r0), "=r"(r1), "=r"(r2), "=r"(r3) : "r"(addr));
}

__device__ __forceinline__ void mma16816(float* c, const u32* a, const u32* b) {
    asm volatile(
        "mma.sync.aligned.m16n8k16.row.col.f32.f16.f16.f32 "
        "{%0,%1,%2,%3}, {%4,%5,%6,%7}, {%8,%9}, {%0,%1,%2,%3};"
        : "+f"(c[0]), "+f"(c[1]), "+f"(c[2]), "+f"(c[3])
        : "r"(a[0]), "r"(a[1]), "r"(a[2]), "r"(a[3]), "r"(b[0]), "r"(b[1]));
}

__device__ __forceinline__ u32 pack_h2(float a, float b) {
    __half2 h = __floats2half2_rn(a, b);
    return *(u32*)&h;
}

// ---------------------------------------------------------------------------
// Kernel 0: fp32 -> fp16 round. which: 0=x, 1=qkv_w, 2=proj_w
// ---------------------------------------------------------------------------
__global__ __launch_bounds__(256) void cvt_round_kernel(
    const float* __restrict__ src, int n, int which)
{
    int i = (blockIdx.x * 256 + threadIdx.x) * 4;
    if (i >= n) return;
    float4 v = *(const float4*)(src + i);
    union { __half h[4]; uint2 u; } uh;
    uh.h[0] = __float2half(v.x); uh.h[1] = __float2half(v.y);
    uh.h[2] = __float2half(v.z); uh.h[3] = __float2half(v.w);
    __half* dst = (which == 0) ? g_x : (which == 1) ? g_qw : g_pw;
    *(uint2*)(dst + i) = uh.u;
}

// ---------------------------------------------------------------------------
// Kernel 1: mma.sync fp16 GEMM.  C[m,o] = sum_k A[m,k] * B[o,k]  (fp32 accum)
// Block 128x128, 8 warps of 64x32, K-slab 64, 2-stage cp.async pipeline.
// smem/stage: 2 arrays (A, B) of 128 rows x 64 fp16, 144B stride.
// mode 0: A=x, B=qkv_w -> Q(*scale)/K [B,H,N,D], Vt [B,H,D,N]
// mode 1: A=attn out, B=proj_w -> +bias, fp32 d_out
// ---------------------------------------------------------------------------
#define ARR_BYTES   18432           // 128 * 144
#define STAGE_BYTES 36864           // 2 arrays
#define SMEM_DYN    73728
#define NSLAB       12              // 768 / 64

__global__ __launch_bounds__(256, 2) void gemm_tc_kernel(
    int mode, const float* __restrict__ bias, float* __restrict__ out)
{
    extern __shared__ char smem_raw[];
    const u32 smem_base = smem_u32(smem_raw);

    const int tid = threadIdx.x;
    const int wid = tid >> 5;
    const int lane = tid & 31;
    const int warp_m = wid >> 2;
    const int warp_n = wid & 3;
    const int m0 = blockIdx.y * 128;
    const int n0 = blockIdx.x * 128;

    const __half *Ap, *Bp;
    if (mode == 0) { Ap = g_x; Bp = g_qw; }
    else           { Ap = g_O; Bp = g_pw; }

    auto load_slab = [&](int st, int kele) {
        const u32 stb = smem_base + st * STAGE_BYTES;
#pragma unroll
        for (int e = tid; e < 2048; e += 256) {
            const int arr = e >> 10;         // 0:A 1:B
            const int i = e & 1023;
            const int row = i >> 3, ch = i & 7;
            const __half* base = arr ? Bp : Ap;
            const int grow = (arr ? n0 : m0) + row;
            const __half* src = base + (size_t)grow * KDIM + kele + ch * 8;
            const u32 dst = stb + arr * ARR_BYTES + row * 144 + ch * 16;
            CP_ASYNC16(dst, src);
        }
    };

    float C[4][4][4];
#pragma unroll
    for (int i = 0; i < 4; i++)
#pragma unroll
        for (int j = 0; j < 4; j++)
#pragma unroll
            for (int r = 0; r < 4; r++) C[i][j][r] = 0.0f;

    load_slab(0, 0);  CP_COMMIT();
    load_slab(1, 64); CP_COMMIT();

    const u32 a_row = warp_m * 64 + (lane & 15);
    const u32 a_colh = ((lane >> 4) & 1) * 16;
    const u32 b_row = warp_n * 32 + (lane & 7) + ((lane & 16) >> 1);
    const u32 b_colh = ((lane >> 3) & 1) * 16;

    for (int s = 0; s < NSLAB; s++) {
        CP_WAIT1();
        __syncthreads();
        const u32 stb = smem_base + (s & 1) * STAGE_BYTES;

#pragma unroll
        for (int kk = 0; kk < 4; kk++) {
            const u32 k0b = kk * 32;

            u32 Bv[4][2];
#pragma unroll
            for (int np = 0; np < 2; np++) {
                const u32 badr = stb + ARR_BYTES +
                                 (b_row + np * 16) * 144 + k0b + b_colh;
                u32 r0, r1, r2, r3;
                ldmx4(r0, r1, r2, r3, badr);
                Bv[np * 2][0] = r0; Bv[np * 2][1] = r1;
                Bv[np * 2 + 1][0] = r2; Bv[np * 2 + 1][1] = r3;
            }

            u32 A[4][4];
#pragma unroll
            for (int ms = 0; ms < 4; ms++) {
                const u32 aoff = (a_row + ms * 16) * 144 + k0b + a_colh;
                ldmx4(A[ms][0], A[ms][1], A[ms][2], A[ms][3], stb + aoff);
            }
#pragma unroll
            for (int ms = 0; ms < 4; ms++)
#pragma unroll
                for (int ns = 0; ns < 4; ns++)
                    mma16816(C[ms][ns], A[ms], Bv[ns]);
        }

        __syncthreads();
        if (s + 2 < NSLAB) load_slab(s & 1, (s + 2) * 64);
        CP_COMMIT();
    }

    const int r_in = lane >> 2;
    const int c_in = (lane & 3) * 2;
#pragma unroll
    for (int ms = 0; ms < 4; ms++) {
#pragma unroll
        for (int ns = 0; ns < 4; ns++) {
            const int col = n0 + warp_n * 32 + ns * 8 + c_in;
#pragma unroll
            for (int half_ = 0; half_ < 2; half_++) {
                const int row = m0 + warp_m * 64 + ms * 16 + r_in + half_ * 8;
                float v0 = C[ms][ns][half_ * 2 + 0];
                float v1 = C[ms][ns][half_ * 2 + 1];
                if (mode == 0) {
                    const int which = col / 768;
                    const int rem = col - which * 768;
                    const int h = rem >> 6, d = rem & 63;
                    const int b = row >> 10, n = row & 1023;
                    if (which == 0) { v0 *= QK_SCALE; v1 *= QK_SCALE; }
                    if (which < 2) {
                        union { __half h[2]; u32 u; } hh;
                        hh.h[0] = __float2half(v0); hh.h[1] = __float2half(v1);
                        const size_t idx = ((size_t)(b * NHEAD + h) * NSEQ + n) * DHEAD + d;
                        __half* dst = (which == 0) ? g_Qh : g_Kh;
                        *(u32*)(dst + idx) = hh.u;
                    } else {
                        const size_t idx = ((size_t)(b * NHEAD + h) * DHEAD + d) * NSEQ + n;
                        g_Vt[idx] = __float2half(v0);
                        g_Vt[idx + NSEQ] = __float2half(v1);
                    }
                } else {
                    const float2 bb = *(const float2*)(bias + col);
                    float2 w = make_float2(v0 + bb.x, v1 + bb.y);
                    *(float2*)(out + (size_t)row * 768 + col) = w;
                }
            }
        }
    }
}

// ---------------------------------------------------------------------------
// Kernel 2: flash attention on tensor cores (fp16 inputs, fp32 softmax/accum).
// 8 warps/CTA, Q-tile 128 (16 rows/warp), K-tile 64, double-buffered cp.async.
// smem: Q (128x144) + 2 stages x {K, Vt} (64x144 each).
// ---------------------------------------------------------------------------
#define FA_Q      18432              // 128 rows * 144B
#define FA_ARR    9216               // 64 rows * 144B
#define FA_STAGE  18432              // 2 arrays (K, Vt)
#define FA_SMEM   (FA_Q + 2 * FA_STAGE)   // 55296

__global__ __launch_bounds__(256) void flash_attn_tc_kernel()
{
    extern __shared__ char smem_raw[];
    const u32 S0 = smem_u32(smem_raw);

    const int tid = threadIdx.x;
    const int w = tid >> 5;
    const int lane = tid & 31;
    const int qt = blockIdx.x;        // 0..7  (Q tiles of 128)
    const int h  = blockIdx.y;
    const int b  = blockIdx.z;
    const size_t bh = (size_t)(b * NHEAD + h);

    const __half* Qg = g_Qh + (bh * NSEQ + qt * 128) * DHEAD;
    const __half* Kg = g_Kh + bh * NSEQ * DHEAD;
    const __half* Vg = g_Vt + bh * DHEAD * NSEQ;

    // Q tile: 128 rows x 8 chunks of 16B
#pragma unroll
    for (int e = tid; e < 1024; e += 256) {
        const int r = e >> 3, ch = e & 7;
        CP_ASYNC16(S0 + r * 144 + ch * 16, Qg + r * DHEAD + ch * 8);
    }

    auto load_kv = [&](int st, int t) {
        const u32 stb = S0 + FA_Q + st * FA_STAGE;
#pragma unroll
        for (int e = tid; e < 1024; e += 256) {
            const int arr = e >> 9;          // 0:K 1:Vt
            const int i = e & 511;
            const int r = i >> 3, ch = i & 7;
            const __half* src;
            if (arr == 0) src = Kg + (size_t)(t * 64 + r) * DHEAD + ch * 8;
            else          src = Vg + (size_t)r * NSEQ + t * 64 + ch * 8;
            CP_ASYNC16(stb + arr * FA_ARR + r * 144 + ch * 16, src);
        }
    };

    load_kv(0, 0); CP_COMMIT();
    load_kv(1, 1); CP_COMMIT();

    float O[8][4];
#pragma unroll
    for (int i = 0; i < 8; i++)
#pragma unroll
        for (int j = 0; j < 4; j++) O[i][j] = 0.0f;
    float m0 = -1e30f, m1 = -1e30f, l0 = 0.0f, l1 = 0.0f;

    const u32 qbase = S0 + w * 16 * 144;
    const u32 a_rowoff = (lane & 15) * 144 + ((lane >> 4) & 1) * 16;
    const u32 b_rowsel = (lane & 7) + ((lane & 16) >> 1);
    const u32 b_colh = ((lane >> 3) & 1) * 16;

    for (int t = 0; t < NSEQ / 64; t++) {
        CP_WAIT1();
        __syncthreads();
        const u32 stb = S0 + FA_Q + (t & 1) * FA_STAGE;
        const u32 K_s = stb, V_s = stb + FA_ARR;

        // ---- S = Q K^T (16x64 per warp) ----
        float Sc[8][4];
#pragma unroll
        for (int j = 0; j < 8; j++)
#pragma unroll
            for (int r = 0; r < 4; r++) Sc[j][r] = 0.0f;

#pragma unroll
        for (int kk = 0; kk < 4; kk++) {
            const u32 k0b = kk * 32;
            u32 Aq[4];
            ldmx4(Aq[0], Aq[1], Aq[2], Aq[3], qbase + a_rowoff + k0b);
#pragma unroll
            for (int kb = 0; kb < 4; kb++) {
                const u32 roff = (kb * 16 + b_rowsel) * 144 + k0b + b_colh;
                u32 r0, r1, r2, r3;
                ldmx4(r0, r1, r2, r3, K_s + roff);
                u32 b0[2] = {r0, r1}, b1[2] = {r2, r3};
                mma16816(Sc[kb * 2],     Aq, b0);
                mma16816(Sc[kb * 2 + 1], Aq, b1);
            }
        }

        // ---- online softmax (rows r0 = lane>>2, r1 = r0+8) ----
        float mx0 = -1e30f, mx1 = -1e30f;
#pragma unroll
        for (int j = 0; j < 8; j++) {
            mx0 = fmaxf(mx0, fmaxf(Sc[j][0], Sc[j][1]));
            mx1 = fmaxf(mx1, fmaxf(Sc[j][2], Sc[j][3]));
        }
        mx0 = fmaxf(mx0, __shfl_xor_sync(0xffffffffu, mx0, 1));
        mx0 = fmaxf(mx0, __shfl_xor_sync(0xffffffffu, mx0, 2));
        mx1 = fmaxf(mx1, __shfl_xor_sync(0xffffffffu, mx1, 1));
        mx1 = fmaxf(mx1, __shfl_xor_sync(0xffffffffu, mx1, 2));

        const float mn0 = fmaxf(m0, mx0), mn1 = fmaxf(m1, mx1);
        const float cr0 = __expf(m0 - mn0), cr1 = __expf(m1 - mn1);
        m0 = mn0; m1 = mn1;

        float rs0 = 0.0f, rs1 = 0.0f;
#pragma unroll
        for (int j = 0; j < 8; j++) {
            Sc[j][0] = __expf(Sc[j][0] - mn0); rs0 += Sc[j][0];
            Sc[j][1] = __expf(Sc[j][1] - mn0); rs0 += Sc[j][1];
            Sc[j][2] = __expf(Sc[j][2] - mn1); rs1 += Sc[j][2];
            Sc[j][3] = __expf(Sc[j][3] - mn1); rs1 += Sc[j][3];
        }
        rs0 += __shfl_xor_sync(0xffffffffu, rs0, 1);
        rs0 += __shfl_xor_sync(0xffffffffu, rs0, 2);
        rs1 += __shfl_xor_sync(0xffffffffu, rs1, 1);
        rs1 += __shfl_xor_sync(0xffffffffu, rs1, 2);
        l0 = l0 * cr0 + rs0;
        l1 = l1 * cr1 + rs1;

#pragma unroll
        for (int d = 0; d < 8; d++) {
            O[d][0] *= cr0; O[d][1] *= cr0;
            O[d][2] *= cr1; O[d][3] *= cr1;
        }

        // ---- P -> fp16 fragments ----
        u32 Pp01[8], Pp23[8];
#pragma unroll
        for (int j = 0; j < 8; j++) {
            Pp01[j] = pack_h2(Sc[j][0], Sc[j][1]);
            Pp23[j] = pack_h2(Sc[j][2], Sc[j][3]);
        }

        // ---- O += P V (16x64 per warp) ----
#pragma unroll
        for (int kk2 = 0; kk2 < 4; kk2++) {
            u32 PA[4] = {Pp01[2 * kk2], Pp23[2 * kk2],
                         Pp01[2 * kk2 + 1], Pp23[2 * kk2 + 1]};
            const u32 k0b = kk2 * 32;
#pragma unroll
            for (int ds = 0; ds < 4; ds++) {
                const u32 roff = (ds * 16 + b_rowsel) * 144 + k0b + b_colh;
                u32 r0, r1, r2, r3;
                ldmx4(r0, r1, r2, r3, V_s + roff);
                u32 v0[2] = {r0, r1}, v1[2] = {r2, r3};
                mma16816(O[ds * 2],     PA, v0);
                mma16816(O[ds * 2 + 1], PA, v1);
            }
        }

        __syncthreads();
        if (t + 2 < NSEQ / 64) load_kv(t & 1, t + 2);
        CP_COMMIT();
    }

    // ---- epilogue: normalize, round fp16, write [B,N,C] ----
    const float inv0 = 1.0f / l0, inv1 = 1.0f / l1;
    const int r0 = lane >> 2;
    const int nrow0 = qt * 128 + w * 16 + r0;
    const int colb = h * 64 + (lane & 3) * 2;
#pragma unroll
    for (int ds = 0; ds < 8; ds++) {
        const int col = colb + ds * 8;
        const u32 u0 = pack_h2(O[ds][0] * inv0, O[ds][1] * inv0);
        const u32 u1 = pack_h2(O[ds][2] * inv1, O[ds][3] * inv1);
        const size_t i0 = (size_t)(b * NSEQ + nrow0) * CDIM + col;
        const size_t i1 = (size_t)(b * NSEQ + nrow0 + 8) * CDIM + col;
        *(u32*)(g_O + i0) = u0;
        *(u32*)(g_O + i1) = u1;
    }
}

// ---------------------------------------------------------------------------
extern "C" void kernel_launch(void* const* d_in, const int* in_sizes, int n_in,
                              void* d_out, int out_size)
{
    const float* x      = (const float*)d_in[0];
    const float* qkv_w  = (const float*)d_in[1];
    const float* proj_w = (const float*)d_in[2];
    const float* proj_b = (const float*)d_in[3];
    float* out = (float*)d_out;

    cudaFuncSetAttribute(gemm_tc_kernel,
                         cudaFuncAttributeMaxDynamicSharedMemorySize, SMEM_DYN);
    cudaFuncSetAttribute(flash_attn_tc_kernel,
                         cudaFuncAttributeMaxDynamicSharedMemorySize, FA_SMEM);

    cvt_round_kernel<<<(MROWS * CDIM) / 1024, 256>>>(x, MROWS * CDIM, 0);
    cvt_round_kernel<<<(3 * CDIM * CDIM) / 1024, 256>>>(qkv_w, 3 * CDIM * CDIM, 1);
    cvt_round_kernel<<<(CDIM * CDIM) / 1024, 256>>>(proj_w, CDIM * CDIM, 2);

    // QKV projection -> Q(*scale)/K, Vt
    gemm_tc_kernel<<<dim3(2304 / 128, MROWS / 128), 256, SMEM_DYN>>>(0, nullptr, nullptr);

    // Flash attention (tensor cores), Q-tile 128
    flash_attn_tc_kernel<<<dim3(NSEQ / 128, NHEAD, BATCH), 256, FA_SMEM>>>();

    // Output projection (+bias) -> d_out
    gemm_tc_kernel<<<dim3(768 / 128, MROWS / 128), 256, SMEM_DYN>>>(1, proj_b, out);
}

// round 9
// speedup vs baseline: 8.2413x; 1.0022x over previous
#include <cuda_runtime.h>
#include <cuda_fp16.h>
#include <cstdint>
#include <math.h>

#define BATCH 8
#define NSEQ  1024
#define CDIM  768
#define NHEAD 12
#define DHEAD 64
#define MROWS 8192
#define KDIM  768
#define QK_SCALE 0.125f

typedef unsigned long long u64;
typedef unsigned int u32;

// ---------------------------------------------------------------------------
// scratch globals (allocation-free) — all single fp16
// ---------------------------------------------------------------------------
__device__ __half g_x[MROWS * CDIM];
__device__ __half g_qw[3 * CDIM * CDIM];
__device__ __half g_pw[CDIM * CDIM];
__device__ __half g_Qh[BATCH * NHEAD * NSEQ * DHEAD];  // pre-scaled
__device__ __half g_Kh[BATCH * NHEAD * NSEQ * DHEAD];
__device__ __half g_Vt[BATCH * NHEAD * DHEAD * NSEQ];  // [B,H,D,N]
__device__ __half g_O[MROWS * CDIM];                   // attn out [B,N,C]

// ---------------------------------------------------------------------------
// PTX helpers — sm_80-era instruction set (valid under compute_103)
// ---------------------------------------------------------------------------
__device__ __forceinline__ u32 smem_u32(const void* p) {
    u32 a;
    asm("{ .reg .u64 t; cvta.to.shared.u64 t, %1; cvt.u32.u64 %0, t; }"
        : "=r"(a) : "l"(p));
    return a;
}

#define CP_ASYNC16(dst, src) \
    asm volatile("cp.async.cg.shared.global [%0], [%1], 16;" \
        :: "r"(dst), "l"(src) : "memory")
#define CP_COMMIT() asm volatile("cp.async.commit_group;" ::: "memory")
#define CP_WAIT2()  asm volatile("cp.async.wait_group 2;" ::: "memory")

__device__ __forceinline__ void ldmx4(u32& r0, u32& r1, u32& r2, u32& r3, u32 addr) {
    asm volatile("ldmatrix.sync.aligned.m8n8.x4.shared.b16 {%0,%1,%2,%3}, [%4];"
        : "=r"(r0), "=r"(r1), "=r"(r2), "=r"(r3) : "r"(addr));
}

__device__ __forceinline__ void mma16816(float* c, const u32* a, const u32* b) {
    asm volatile(
        "mma.sync.aligned.m16n8k16.row.col.f32.f16.f16.f32 "
        "{%0,%1,%2,%3}, {%4,%5,%6,%7}, {%8,%9}, {%0,%1,%2,%3};"
        : "+f"(c[0]), "+f"(c[1]), "+f"(c[2]), "+f"(c[3])
        : "r"(a[0]), "r"(a[1]), "r"(a[2]), "r"(a[3]), "r"(b[0]), "r"(b[1]));
}

__device__ __forceinline__ u32 pack_h2(float a, float b) {
    __half2 h = __floats2half2_rn(a, b);
    return *(u32*)&h;
}

// ---------------------------------------------------------------------------
// Kernel 0: fused fp32 -> fp16 round for x, qkv_w, proj_w (one launch)
// ---------------------------------------------------------------------------
#define N_X  (MROWS * CDIM)
#define N_QW (3 * CDIM * CDIM)
#define N_PW (CDIM * CDIM)

__global__ __launch_bounds__(256) void cvt_all_kernel(
    const float* __restrict__ x, const float* __restrict__ qw,
    const float* __restrict__ pw)
{
    int i = (blockIdx.x * 256 + threadIdx.x) * 4;
    const float* src;
    __half* dst;
    if (i < N_X)                { src = x + i;               dst = g_x + i; }
    else if (i < N_X + N_QW)    { src = qw + (i - N_X);      dst = g_qw + (i - N_X); }
    else if (i < N_X + N_QW + N_PW) { src = pw + (i - N_X - N_QW); dst = g_pw + (i - N_X - N_QW); }
    else return;
    float4 v = *(const float4*)src;
    union { __half h[4]; uint2 u; } uh;
    uh.h[0] = __float2half(v.x); uh.h[1] = __float2half(v.y);
    uh.h[2] = __float2half(v.z); uh.h[3] = __float2half(v.w);
    *(uint2*)dst = uh.u;
}

// ---------------------------------------------------------------------------
// Kernel 1: mma.sync fp16 GEMM.  C[m,o] = sum_k A[m,k] * B[o,k]  (fp32 accum)
// Block 128x128, 8 warps of 64x32, K-slab 64, 3-stage cp.async pipeline.
// smem/stage: 2 arrays (A, B) of 128 rows x 64 fp16, 144B stride.
// mode 0: A=x, B=qkv_w -> Q(*scale)/K [B,H,N,D], Vt [B,H,D,N]
// mode 1: A=attn out, B=proj_w -> +bias, fp32 d_out
// ---------------------------------------------------------------------------
#define ARR_BYTES   18432           // 128 * 144
#define STAGE_BYTES 36864           // 2 arrays
#define SMEM_DYN    110592          // 3 stages
#define NSLAB       12              // 768 / 64

__global__ __launch_bounds__(256, 2) void gemm_tc_kernel(
    int mode, const float* __restrict__ bias, float* __restrict__ out)
{
    extern __shared__ char smem_raw[];
    const u32 smem_base = smem_u32(smem_raw);

    const int tid = threadIdx.x;
    const int wid = tid >> 5;
    const int lane = tid & 31;
    const int warp_m = wid >> 2;
    const int warp_n = wid & 3;
    const int m0 = blockIdx.y * 128;
    const int n0 = blockIdx.x * 128;

    const __half *Ap, *Bp;
    if (mode == 0) { Ap = g_x; Bp = g_qw; }
    else           { Ap = g_O; Bp = g_pw; }

    auto load_slab = [&](int st, int kele) {
        const u32 stb = smem_base + st * STAGE_BYTES;
#pragma unroll
        for (int e = tid; e < 2048; e += 256) {
            const int arr = e >> 10;         // 0:A 1:B
            const int i = e & 1023;
            const int row = i >> 3, ch = i & 7;
            const __half* base = arr ? Bp : Ap;
            const int grow = (arr ? n0 : m0) + row;
            const __half* src = base + (size_t)grow * KDIM + kele + ch * 8;
            const u32 dst = stb + arr * ARR_BYTES + row * 144 + ch * 16;
            CP_ASYNC16(dst, src);
        }
    };

    float C[4][4][4];
#pragma unroll
    for (int i = 0; i < 4; i++)
#pragma unroll
        for (int j = 0; j < 4; j++)
#pragma unroll
            for (int r = 0; r < 4; r++) C[i][j][r] = 0.0f;

    load_slab(0, 0);   CP_COMMIT();
    load_slab(1, 64);  CP_COMMIT();
    load_slab(2, 128); CP_COMMIT();

    const u32 a_row = warp_m * 64 + (lane & 15);
    const u32 a_colh = ((lane >> 4) & 1) * 16;
    const u32 b_row = warp_n * 32 + (lane & 7) + ((lane & 16) >> 1);
    const u32 b_colh = ((lane >> 3) & 1) * 16;

    int stage = 0;
    for (int s = 0; s < NSLAB; s++) {
        CP_WAIT2();
        __syncthreads();
        const u32 stb = smem_base + stage * STAGE_BYTES;

#pragma unroll
        for (int kk = 0; kk < 4; kk++) {
            const u32 k0b = kk * 32;

            u32 Bv[4][2];
#pragma unroll
            for (int np = 0; np < 2; np++) {
                const u32 badr = stb + ARR_BYTES +
                                 (b_row + np * 16) * 144 + k0b + b_colh;
                u32 r0, r1, r2, r3;
                ldmx4(r0, r1, r2, r3, badr);
                Bv[np * 2][0] = r0; Bv[np * 2][1] = r1;
                Bv[np * 2 + 1][0] = r2; Bv[np * 2 + 1][1] = r3;
            }

            u32 A[4][4];
#pragma unroll
            for (int ms = 0; ms < 4; ms++) {
                const u32 aoff = (a_row + ms * 16) * 144 + k0b + a_colh;
                ldmx4(A[ms][0], A[ms][1], A[ms][2], A[ms][3], stb + aoff);
            }
#pragma unroll
            for (int ms = 0; ms < 4; ms++)
#pragma unroll
                for (int ns = 0; ns < 4; ns++)
                    mma16816(C[ms][ns], A[ms], Bv[ns]);
        }

        __syncthreads();
        if (s + 3 < NSLAB) load_slab(stage, (s + 3) * 64);
        CP_COMMIT();
        stage = (stage == 2) ? 0 : stage + 1;
    }

    const int r_in = lane >> 2;
    const int c_in = (lane & 3) * 2;
#pragma unroll
    for (int ms = 0; ms < 4; ms++) {
#pragma unroll
        for (int ns = 0; ns < 4; ns++) {
            const int col = n0 + warp_n * 32 + ns * 8 + c_in;
#pragma unroll
            for (int half_ = 0; half_ < 2; half_++) {
                const int row = m0 + warp_m * 64 + ms * 16 + r_in + half_ * 8;
                float v0 = C[ms][ns][half_ * 2 + 0];
                float v1 = C[ms][ns][half_ * 2 + 1];
                if (mode == 0) {
                    const int which = col / 768;
                    const int rem = col - which * 768;
                    const int h = rem >> 6, d = rem & 63;
                    const int b = row >> 10, n = row & 1023;
                    if (which == 0) { v0 *= QK_SCALE; v1 *= QK_SCALE; }
                    if (which < 2) {
                        union { __half h[2]; u32 u; } hh;
                        hh.h[0] = __float2half(v0); hh.h[1] = __float2half(v1);
                        const size_t idx = ((size_t)(b * NHEAD + h) * NSEQ + n) * DHEAD + d;
                        __half* dst = (which == 0) ? g_Qh : g_Kh;
                        *(u32*)(dst + idx) = hh.u;
                    } else {
                        const size_t idx = ((size_t)(b * NHEAD + h) * DHEAD + d) * NSEQ + n;
                        g_Vt[idx] = __float2half(v0);
                        g_Vt[idx + NSEQ] = __float2half(v1);
                    }
                } else {
                    const float2 bb = *(const float2*)(bias + col);
                    float2 w = make_float2(v0 + bb.x, v1 + bb.y);
                    *(float2*)(out + (size_t)row * 768 + col) = w;
                }
            }
        }
    }
}

// ---------------------------------------------------------------------------
// Kernel 2: flash attention on tensor cores (fp16 inputs, fp32 softmax/accum).
// 8 warps/CTA, Q-tile 128 (16 rows/warp), K-tile 64, 3-stage cp.async.
// smem: Q (128x144) + 3 stages x {K, Vt} (64x144 each).
// ---------------------------------------------------------------------------
#define FA_Q      18432              // 128 rows * 144B
#define FA_ARR    9216               // 64 rows * 144B
#define FA_STAGE  18432              // 2 arrays (K, Vt)
#define FA_SMEM   (FA_Q + 3 * FA_STAGE)   // 73728
#define NT        (NSEQ / 64)        // 16

__global__ __launch_bounds__(256) void flash_attn_tc_kernel()
{
    extern __shared__ char smem_raw[];
    const u32 S0 = smem_u32(smem_raw);

    const int tid = threadIdx.x;
    const int w = tid >> 5;
    const int lane = tid & 31;
    const int qt = blockIdx.x;        // 0..7  (Q tiles of 128)
    const int h  = blockIdx.y;
    const int b  = blockIdx.z;
    const size_t bh = (size_t)(b * NHEAD + h);

    const __half* Qg = g_Qh + (bh * NSEQ + qt * 128) * DHEAD;
    const __half* Kg = g_Kh + bh * NSEQ * DHEAD;
    const __half* Vg = g_Vt + bh * DHEAD * NSEQ;

    // Q tile: 128 rows x 8 chunks of 16B (part of commit group 0)
#pragma unroll
    for (int e = tid; e < 1024; e += 256) {
        const int r = e >> 3, ch = e & 7;
        CP_ASYNC16(S0 + r * 144 + ch * 16, Qg + r * DHEAD + ch * 8);
    }

    auto load_kv = [&](int st, int t) {
        const u32 stb = S0 + FA_Q + st * FA_STAGE;
#pragma unroll
        for (int e = tid; e < 1024; e += 256) {
            const int arr = e >> 9;          // 0:K 1:Vt
            const int i = e & 511;
            const int r = i >> 3, ch = i & 7;
            const __half* src;
            if (arr == 0) src = Kg + (size_t)(t * 64 + r) * DHEAD + ch * 8;
            else          src = Vg + (size_t)r * NSEQ + t * 64 + ch * 8;
            CP_ASYNC16(stb + arr * FA_ARR + r * 144 + ch * 16, src);
        }
    };

    load_kv(0, 0); CP_COMMIT();
    load_kv(1, 1); CP_COMMIT();
    load_kv(2, 2); CP_COMMIT();

    float O[8][4];
#pragma unroll
    for (int i = 0; i < 8; i++)
#pragma unroll
        for (int j = 0; j < 4; j++) O[i][j] = 0.0f;
    float m0 = -1e30f, m1 = -1e30f, l0 = 0.0f, l1 = 0.0f;

    const u32 qbase = S0 + w * 16 * 144;
    const u32 a_rowoff = (lane & 15) * 144 + ((lane >> 4) & 1) * 16;
    const u32 b_rowsel = (lane & 7) + ((lane & 16) >> 1);
    const u32 b_colh = ((lane >> 3) & 1) * 16;

    int stage = 0;
    for (int t = 0; t < NT; t++) {
        CP_WAIT2();
        __syncthreads();
        const u32 stb = S0 + FA_Q + stage * FA_STAGE;
        const u32 K_s = stb, V_s = stb + FA_ARR;

        // ---- S = Q K^T (16x64 per warp) ----
        float Sc[8][4];
#pragma unroll
        for (int j = 0; j < 8; j++)
#pragma unroll
            for (int r = 0; r < 4; r++) Sc[j][r] = 0.0f;

#pragma unroll
        for (int kk = 0; kk < 4; kk++) {
            const u32 k0b = kk * 32;
            u32 Aq[4];
            ldmx4(Aq[0], Aq[1], Aq[2], Aq[3], qbase + a_rowoff + k0b);
#pragma unroll
            for (int kb = 0; kb < 4; kb++) {
                const u32 roff = (kb * 16 + b_rowsel) * 144 + k0b + b_colh;
                u32 r0, r1, r2, r3;
                ldmx4(r0, r1, r2, r3, K_s + roff);
                u32 b0[2] = {r0, r1}, b1[2] = {r2, r3};
                mma16816(Sc[kb * 2],     Aq, b0);
                mma16816(Sc[kb * 2 + 1], Aq, b1);
            }
        }

        // ---- online softmax (rows r0 = lane>>2, r1 = r0+8) ----
        float mx0 = -1e30f, mx1 = -1e30f;
#pragma unroll
        for (int j = 0; j < 8; j++) {
            mx0 = fmaxf(mx0, fmaxf(Sc[j][0], Sc[j][1]));
            mx1 = fmaxf(mx1, fmaxf(Sc[j][2], Sc[j][3]));
        }
        mx0 = fmaxf(mx0, __shfl_xor_sync(0xffffffffu, mx0, 1));
        mx0 = fmaxf(mx0, __shfl_xor_sync(0xffffffffu, mx0, 2));
        mx1 = fmaxf(mx1, __shfl_xor_sync(0xffffffffu, mx1, 1));
        mx1 = fmaxf(mx1, __shfl_xor_sync(0xffffffffu, mx1, 2));

        const float mn0 = fmaxf(m0, mx0), mn1 = fmaxf(m1, mx1);
        const float cr0 = __expf(m0 - mn0), cr1 = __expf(m1 - mn1);
        m0 = mn0; m1 = mn1;

        float rs0 = 0.0f, rs1 = 0.0f;
#pragma unroll
        for (int j = 0; j < 8; j++) {
            Sc[j][0] = __expf(Sc[j][0] - mn0); rs0 += Sc[j][0];
            Sc[j][1] = __expf(Sc[j][1] - mn0); rs0 += Sc[j][1];
            Sc[j][2] = __expf(Sc[j][2] - mn1); rs1 += Sc[j][2];
            Sc[j][3] = __expf(Sc[j][3] - mn1); rs1 += Sc[j][3];
        }
        rs0 += __shfl_xor_sync(0xffffffffu, rs0, 1);
        rs0 += __shfl_xor_sync(0xffffffffu, rs0, 2);
        rs1 += __shfl_xor_sync(0xffffffffu, rs1, 1);
        rs1 += __shfl_xor_sync(0xffffffffu, rs1, 2);
        l0 = l0 * cr0 + rs0;
        l1 = l1 * cr1 + rs1;

#pragma unroll
        for (int d = 0; d < 8; d++) {
            O[d][0] *= cr0; O[d][1] *= cr0;
            O[d][2] *= cr1; O[d][3] *= cr1;
        }

        // ---- P -> fp16 fragments ----
        u32 Pp01[8], Pp23[8];
#pragma unroll
        for (int j = 0; j < 8; j++) {
            Pp01[j] = pack_h2(Sc[j][0], Sc[j][1]);
            Pp23[j] = pack_h2(Sc[j][2], Sc[j][3]);
        }

        // ---- O += P V (16x64 per warp) ----
#pragma unroll
        for (int kk2 = 0; kk2 < 4; kk2++) {
            u32 PA[4] = {Pp01[2 * kk2], Pp23[2 * kk2],
                         Pp01[2 * kk2 + 1], Pp23[2 * kk2 + 1]};
            const u32 k0b = kk2 * 32;
#pragma unroll
            for (int ds = 0; ds < 4; ds++) {
                const u32 roff = (ds * 16 + b_rowsel) * 144 + k0b + b_colh;
                u32 r0, r1, r2, r3;
                ldmx4(r0, r1, r2, r3, V_s + roff);
                u32 v0[2] = {r0, r1}, v1[2] = {r2, r3};
                mma16816(O[ds * 2],     PA, v0);
                mma16816(O[ds * 2 + 1], PA, v1);
            }
        }

        __syncthreads();
        if (t + 3 < NT) load_kv(stage, t + 3);
        CP_COMMIT();
        stage = (stage == 2) ? 0 : stage + 1;
    }

    // ---- epilogue: normalize, round fp16, write [B,N,C] ----
    const float inv0 = 1.0f / l0, inv1 = 1.0f / l1;
    const int r0 = lane >> 2;
    const int nrow0 = qt * 128 + w * 16 + r0;
    const int colb = h * 64 + (lane & 3) * 2;
#pragma unroll
    for (int ds = 0; ds < 8; ds++) {
        const int col = colb + ds * 8;
        const u32 u0 = pack_h2(O[ds][0] * inv0, O[ds][1] * inv0);
        const u32 u1 = pack_h2(O[ds][2] * inv1, O[ds][3] * inv1);
        const size_t i0 = (size_t)(b * NSEQ + nrow0) * CDIM + col;
        const size_t i1 = (size_t)(b * NSEQ + nrow0 + 8) * CDIM + col;
        *(u32*)(g_O + i0) = u0;
        *(u32*)(g_O + i1) = u1;
    }
}

// ---------------------------------------------------------------------------
extern "C" void kernel_launch(void* const* d_in, const int* in_sizes, int n_in,
                              void* d_out, int out_size)
{
    const float* x      = (const float*)d_in[0];
    const float* qkv_w  = (const float*)d_in[1];
    const float* proj_w = (const float*)d_in[2];
    const float* proj_b = (const float*)d_in[3];
    float* out = (float*)d_out;

    cudaFuncSetAttribute(gemm_tc_kernel,
                         cudaFuncAttributeMaxDynamicSharedMemorySize, SMEM_DYN);
    cudaFuncSetAttribute(flash_attn_tc_kernel,
                         cudaFuncAttributeMaxDynamicSharedMemorySize, FA_SMEM);

    const int ncvt = (N_X + N_QW + N_PW) / 4;
    cvt_all_kernel<<<(ncvt + 255) / 256, 256>>>(x, qkv_w, proj_w);

    // QKV projection -> Q(*scale)/K, Vt
    gemm_tc_kernel<<<dim3(2304 / 128, MROWS / 128), 256, SMEM_DYN>>>(0, nullptr, nullptr);

    // Flash attention (tensor cores), Q-tile 128
    flash_attn_tc_kernel<<<dim3(NSEQ / 128, NHEAD, BATCH), 256, FA_SMEM>>>();

    // Output projection (+bias) -> d_out
    gemm_tc_kernel<<<dim3(768 / 128, MROWS / 128), 256, SMEM_DYN>>>(1, proj_b, out);
}